// round 5
// baseline (speedup 1.0000x reference)
#include <cuda_runtime.h>
#include <cstdint>

// Problem dims (fixed)
static constexpr int T = 1024, B = 32, S = 2048, D = 512;
static constexpr float LN_EPS = 1e-6f;

// Scratch: linear+LN output [B][T][D]
__device__ __align__(256) float g_X[(size_t)B * T * D];

// ---------------------------------------------------------------------------
__device__ __forceinline__ float f2tf(float x) {
    uint32_t r; asm("cvt.rna.tf32.f32 %0, %1;" : "=r"(r) : "f"(x));
    return __uint_as_float(r);
}
__device__ __forceinline__ void mma8(float* d, const uint32_t* a, const uint32_t* b) {
    asm volatile(
        "mma.sync.aligned.m16n8k8.row.col.f32.tf32.tf32.f32 "
        "{%0,%1,%2,%3}, {%4,%5,%6,%7}, {%8,%9}, {%0,%1,%2,%3};"
        : "+f"(d[0]), "+f"(d[1]), "+f"(d[2]), "+f"(d[3])
        : "r"(a[0]), "r"(a[1]), "r"(a[2]), "r"(a[3]), "r"(b[0]), "r"(b[1]));
}

// ---------------------------------------------------------------------------
// Split-TF32 GEMM, CTA tile 128x128, KC=32, 512 threads (16 warps, 4x4 grid,
// warp tile 32x32), double-buffered raw-fp32 smem in fragment-major layout,
// 3xTF32 split performed at fragment load.
// MODE 0: linear  C[M,N] = inp(row b*T+t)[M,K] * W[N,K]^T      K=512 (NT)
// MODE 1: scores  C = g_X[M,K] * ctx[N,K]^T                    K=512 (NT)
// MODE 2: AV      C = attn[M,K] * values[K,N]                  K=2048 (NN)
//
// Fragment layout (per 128x32 tile):
//  A float4 id  = (mt*4 + ks)*32 + gr*4 + gc ; elements ordered {m8=0,k4=0},
//                 {m8=1,k4=0},{m8=0,k4=1},{m8=1,k4=1}  (matches mma A frag)
//  B float2 id  = (nt*4 + ks)*32 + gr*4 + gc ; elements {k4=0, k4=1}
// ---------------------------------------------------------------------------
static constexpr int KC = 32;
static constexpr int TILE_FLOATS = 128 * KC;                 // 4096
static constexpr int STAGE_FLOATS = 2 * TILE_FLOATS;         // A + B = 8192
static constexpr int GEMM_SMEM = 2 * STAGE_FLOATS * 4;       // 65536 bytes

template <int MODE>
__global__ __launch_bounds__(512, 1) void k_gemm(const float* __restrict__ Ap,
                                                 const float* __restrict__ Bp,
                                                 float* __restrict__ Cp) {
    extern __shared__ float sm[];

    constexpr int KTOT = (MODE == 2) ? S : D;
    constexpr int NC = KTOT / KC;

    const int tid = threadIdx.x;
    const int n0 = blockIdx.x * 128;
    const int m0 = blockIdx.y * 128;
    const int bz = blockIdx.z;

    const float* Abase; size_t a_rs;
    const float* Bbase; size_t b_rs;
    float* Cbase; size_t c_rs;
    if (MODE == 0) {
        const int bb = m0 >> 10, t0 = m0 & 1023;
        Abase = Ap + ((size_t)t0 * B + bb) * D; a_rs = (size_t)B * D;
        Bbase = Bp + (size_t)n0 * D;            b_rs = D;
        Cbase = g_X + (size_t)m0 * D + n0;      c_rs = D;
    } else if (MODE == 1) {
        Abase = g_X + ((size_t)bz * T + m0) * D;     a_rs = D;
        Bbase = Bp + ((size_t)bz * S + n0) * D;      b_rs = D;
        Cbase = Cp + ((size_t)bz * T + m0) * S + n0; c_rs = S;
    } else {
        Abase = Ap + ((size_t)bz * T + m0) * S;      a_rs = S;
        Bbase = Bp + (size_t)bz * S * D + n0;        b_rs = D;   // values [S][D]
        Cbase = Cp + (size_t)m0 * B * D + (size_t)bz * D + n0; c_rs = (size_t)B * D;
    }

    const int lane = tid & 31, wid = tid >> 5;
    const int gr = lane >> 2, gc = lane & 3;
    const int m_w = (wid >> 2) * 32;   // warp m origin (4 m-groups)
    const int n_w = (wid & 3) * 32;    // warp n origin (4 n-groups)

    // Producer coords: two float4s per tile per thread (ids tid, tid+512)
    float4 na[2], nb[2];

    auto loadAB = [&](int c) {
        const int k0 = c * KC;
        #pragma unroll
        for (int j = 0; j < 2; j++) {
            const int id = tid + 512 * j;
            const int row = id >> 3, q = id & 7;           // NT: row, k-quad
            na[j] = *reinterpret_cast<const float4*>(Abase + (size_t)row * a_rs + k0 + q * 4);
            if (MODE != 2) {
                nb[j] = *reinterpret_cast<const float4*>(Bbase + (size_t)row * b_rs + k0 + q * 4);
            } else {
                const int kk = id >> 5, nq = id & 31;       // NN: k row, n-quad
                nb[j] = *reinterpret_cast<const float4*>(Bbase + (size_t)(k0 + kk) * b_rs + nq * 4);
            }
        }
    };
    auto stsAB = [&](int s) {
        float* sA = sm + s * STAGE_FLOATS;
        float* sB = sA + TILE_FLOATS;
        #pragma unroll
        for (int j = 0; j < 2; j++) {
            const int id = tid + 512 * j;
            {   // A (NT rows always)
                const int row = id >> 3, q = id & 7;
                const int mt = row >> 4, m8 = (row >> 3) & 1, g = row & 7;
                const int ks = q >> 1, k4 = q & 1;
                const int base = (((mt * 4 + ks) * 32 + g * 4) << 2) + k4 * 2 + m8;
                const float4 v = na[j];
                sA[base + 0]  = v.x;
                sA[base + 4]  = v.y;
                sA[base + 8]  = v.z;
                sA[base + 12] = v.w;
            }
            if (MODE != 2) {   // B NT
                const int row = id >> 3, q = id & 7;
                const int nt = row >> 3, g = row & 7;
                const int ks = q >> 1, k4 = q & 1;
                const int base = (((nt * 4 + ks) * 32 + g * 4) << 1) + k4;
                const float4 v = nb[j];
                sB[base + 0] = v.x;
                sB[base + 2] = v.y;
                sB[base + 4] = v.z;
                sB[base + 6] = v.w;
            } else {           // B NN (values rows)
                const int kk = id >> 5, nq = id & 31;
                const int ks = kk >> 3, k4 = (kk >> 2) & 1, c4 = kk & 3;
                const int nt = nq >> 1, g0 = (nq & 1) * 4;
                const int base = (((nt * 4 + ks) * 32 + g0 * 4 + c4) << 1) + k4;
                const float4 v = nb[j];
                sB[base + 0]  = v.x;
                sB[base + 8]  = v.y;
                sB[base + 16] = v.z;
                sB[base + 24] = v.w;
            }
        }
    };

    float acc[2][4][4];
    #pragma unroll
    for (int i = 0; i < 2; i++)
        #pragma unroll
        for (int j = 0; j < 4; j++)
            #pragma unroll
            for (int q = 0; q < 4; q++) acc[i][j][q] = 0.f;

    loadAB(0);
    stsAB(0);
    __syncthreads();

    for (int c = 0; c < NC; c++) {
        const int s = c & 1;
        if (c + 1 < NC) loadAB(c + 1);

        const float* sA = sm + s * STAGE_FLOATS;
        const float* sB = sA + TILE_FLOATS;

        #pragma unroll
        for (int ks = 0; ks < 4; ks++) {
            uint32_t ah[2][4], al[2][4], bh[4][2], bl[4][2];
            #pragma unroll
            for (int mf = 0; mf < 2; mf++) {
                const int mt = (m_w >> 4) + mf;
                const float4 r = *reinterpret_cast<const float4*>(
                    sA + (((mt * 4 + ks) * 32 + gr * 4 + gc) << 2));
                float h;
                h = f2tf(r.x); ah[mf][0] = __float_as_uint(h); al[mf][0] = __float_as_uint(f2tf(r.x - h));
                h = f2tf(r.y); ah[mf][1] = __float_as_uint(h); al[mf][1] = __float_as_uint(f2tf(r.y - h));
                h = f2tf(r.z); ah[mf][2] = __float_as_uint(h); al[mf][2] = __float_as_uint(f2tf(r.z - h));
                h = f2tf(r.w); ah[mf][3] = __float_as_uint(h); al[mf][3] = __float_as_uint(f2tf(r.w - h));
            }
            #pragma unroll
            for (int nf = 0; nf < 4; nf++) {
                const int nt = (n_w >> 3) + nf;
                const float2 r = *reinterpret_cast<const float2*>(
                    sB + (((nt * 4 + ks) * 32 + gr * 4 + gc) << 1));
                float h;
                h = f2tf(r.x); bh[nf][0] = __float_as_uint(h); bl[nf][0] = __float_as_uint(f2tf(r.x - h));
                h = f2tf(r.y); bh[nf][1] = __float_as_uint(h); bl[nf][1] = __float_as_uint(f2tf(r.y - h));
            }
            #pragma unroll
            for (int mf = 0; mf < 2; mf++)
                #pragma unroll
                for (int nf = 0; nf < 4; nf++) {
                    mma8(acc[mf][nf], ah[mf], bh[nf]);
                    mma8(acc[mf][nf], al[mf], bh[nf]);
                    mma8(acc[mf][nf], ah[mf], bl[nf]);
                }
        }
        if (c + 1 < NC) stsAB(s ^ 1);
        __syncthreads();
    }

    // Epilogue
    #pragma unroll
    for (int mf = 0; mf < 2; mf++)
        #pragma unroll
        for (int nf = 0; nf < 4; nf++) {
            const int mrow = m_w + mf * 16 + gr;
            const int ncol = n_w + nf * 8 + 2 * gc;
            float2 v0 = make_float2(acc[mf][nf][0], acc[mf][nf][1]);
            float2 v1 = make_float2(acc[mf][nf][2], acc[mf][nf][3]);
            *reinterpret_cast<float2*>(Cbase + (size_t)mrow * c_rs + ncol) = v0;
            *reinterpret_cast<float2*>(Cbase + (size_t)(mrow + 8) * c_rs + ncol) = v1;
        }
}

// ---------------------------------------------------------------------------
// LayerNorm in place on g_X rows (B*T rows of D)
// ---------------------------------------------------------------------------
__global__ __launch_bounds__(256) void k_ln(const float* __restrict__ gamma,
                                            const float* __restrict__ beta) {
    const int row = blockIdx.x;
    float* x = &g_X[(size_t)row * D];
    const int tid = threadIdx.x;

    float2 v = *reinterpret_cast<const float2*>(&x[tid * 2]);
    float s = v.x + v.y;
    float q = v.x * v.x + v.y * v.y;

    __shared__ float sh_s[8], sh_q[8];
    #pragma unroll
    for (int o = 16; o > 0; o >>= 1) {
        s += __shfl_xor_sync(0xffffffffu, s, o);
        q += __shfl_xor_sync(0xffffffffu, q, o);
    }
    if ((tid & 31) == 0) { sh_s[tid >> 5] = s; sh_q[tid >> 5] = q; }
    __syncthreads();
    float ts = 0.f, tq = 0.f;
    #pragma unroll
    for (int i = 0; i < 8; i++) { ts += sh_s[i]; tq += sh_q[i]; }

    const float mean = ts * (1.0f / D);
    const float var = tq * (1.0f / D) - mean * mean;
    const float rstd = rsqrtf(var + LN_EPS);

    float2 g = *reinterpret_cast<const float2*>(&gamma[tid * 2]);
    float2 bb = *reinterpret_cast<const float2*>(&beta[tid * 2]);
    float2 o;
    o.x = g.x * (v.x - mean) * rstd + bb.x;
    o.y = g.y * (v.y - mean) * rstd + bb.y;
    *reinterpret_cast<float2*>(&x[tid * 2]) = o;
}

// ---------------------------------------------------------------------------
// Softmax over S for each of B*T rows, in place
// ---------------------------------------------------------------------------
__global__ __launch_bounds__(256) void k_softmax(float* __restrict__ attn) {
    const size_t row = blockIdx.x;
    float* p = attn + row * (size_t)S;
    const int tid = threadIdx.x;

    float4 v0 = reinterpret_cast<const float4*>(p)[tid * 2 + 0];
    float4 v1 = reinterpret_cast<const float4*>(p)[tid * 2 + 1];

    float m = fmaxf(fmaxf(fmaxf(v0.x, v0.y), fmaxf(v0.z, v0.w)),
                    fmaxf(fmaxf(v1.x, v1.y), fmaxf(v1.z, v1.w)));
    __shared__ float sh[8];
    #pragma unroll
    for (int o = 16; o > 0; o >>= 1) m = fmaxf(m, __shfl_xor_sync(0xffffffffu, m, o));
    if ((tid & 31) == 0) sh[tid >> 5] = m;
    __syncthreads();
    float gm = sh[0];
    #pragma unroll
    for (int i = 1; i < 8; i++) gm = fmaxf(gm, sh[i]);
    __syncthreads();

    v0.x = __expf(v0.x - gm); v0.y = __expf(v0.y - gm);
    v0.z = __expf(v0.z - gm); v0.w = __expf(v0.w - gm);
    v1.x = __expf(v1.x - gm); v1.y = __expf(v1.y - gm);
    v1.z = __expf(v1.z - gm); v1.w = __expf(v1.w - gm);

    float s = v0.x + v0.y + v0.z + v0.w + v1.x + v1.y + v1.z + v1.w;
    #pragma unroll
    for (int o = 16; o > 0; o >>= 1) s += __shfl_xor_sync(0xffffffffu, s, o);
    if ((tid & 31) == 0) sh[tid >> 5] = s;
    __syncthreads();
    float gs = 0.f;
    #pragma unroll
    for (int i = 0; i < 8; i++) gs += sh[i];
    const float inv = 1.0f / gs;

    v0.x *= inv; v0.y *= inv; v0.z *= inv; v0.w *= inv;
    v1.x *= inv; v1.y *= inv; v1.z *= inv; v1.w *= inv;
    reinterpret_cast<float4*>(p)[tid * 2 + 0] = v0;
    reinterpret_cast<float4*>(p)[tid * 2 + 1] = v1;
}

// ---------------------------------------------------------------------------
extern "C" void kernel_launch(void* const* d_in, const int* in_sizes, int n_in,
                              void* d_out, int out_size) {
    const float* inp    = (const float*)d_in[0];  // [T,B,D]
    const float* ctx    = (const float*)d_in[1];  // [B,S,D]
    const float* values = (const float*)d_in[2];  // [B,S,D]
    const float* W      = (const float*)d_in[3];  // [D,D]
    const float* gamma  = (const float*)d_in[4];  // [D]
    const float* beta   = (const float*)d_in[5];  // [D]

    float* out_wc   = (float*)d_out;                       // [T,B,D]
    float* out_attn = (float*)d_out + (size_t)T * B * D;   // [B*T,S]

    cudaFuncSetAttribute(k_gemm<0>, cudaFuncAttributeMaxDynamicSharedMemorySize, GEMM_SMEM);
    cudaFuncSetAttribute(k_gemm<1>, cudaFuncAttributeMaxDynamicSharedMemorySize, GEMM_SMEM);
    cudaFuncSetAttribute(k_gemm<2>, cudaFuncAttributeMaxDynamicSharedMemorySize, GEMM_SMEM);

    // 1) linear: g_X = inp @ W^T (rows b*T+t)
    {
        dim3 grid(D / 128, (B * T) / 128, 1);
        k_gemm<0><<<grid, 512, GEMM_SMEM>>>(inp, W, nullptr);
    }
    // 2) LayerNorm in place
    k_ln<<<B * T, 256>>>(gamma, beta);
    // 3) scores -> attn region
    {
        dim3 grid(S / 128, T / 128, B);
        k_gemm<1><<<grid, 512, GEMM_SMEM>>>(nullptr, ctx, out_attn);
    }
    // 4) softmax in place
    k_softmax<<<B * T, 256>>>(out_attn);
    // 5) weightedContext (NN: B = values directly)
    {
        dim3 grid(D / 128, T / 128, B);
        k_gemm<2><<<grid, 512, GEMM_SMEM>>>(out_attn, values, out_wc);
    }
}

// round 6
// speedup vs baseline: 1.6134x; 1.6134x over previous
#include <cuda_runtime.h>
#include <cstdint>

// Problem dims (fixed)
static constexpr int T = 1024, B = 32, S = 2048, D = 512;
static constexpr float LN_EPS = 1e-6f;

// Scratch: linear+LN output [B][T][D]
__device__ __align__(256) float g_X[(size_t)B * T * D];

// ---------------------------------------------------------------------------
__device__ __forceinline__ float f2tf(float x) {
    uint32_t r; asm("cvt.rna.tf32.f32 %0, %1;" : "=r"(r) : "f"(x));
    return __uint_as_float(r);
}
__device__ __forceinline__ void mma8(float* d, const uint32_t* a, const uint32_t* b) {
    asm volatile(
        "mma.sync.aligned.m16n8k8.row.col.f32.tf32.tf32.f32 "
        "{%0,%1,%2,%3}, {%4,%5,%6,%7}, {%8,%9}, {%0,%1,%2,%3};"
        : "+f"(d[0]), "+f"(d[1]), "+f"(d[2]), "+f"(d[3])
        : "r"(a[0]), "r"(a[1]), "r"(a[2]), "r"(a[3]), "r"(b[0]), "r"(b[1]));
}

// ---------------------------------------------------------------------------
// Split-TF32 GEMM, CTA tile 64(M)x128(N), KC=32, double-buffered smem,
// 256 threads = 8 warps (2x4), warp tile 32x32, 2 CTAs/SM.
// MODE 0: linear  C[M,N] = inp(row b*T+t)[M,K] * W[N,K]^T      K=512 (NT)
// MODE 1: scores  C = g_X[M,K] * ctx[N,K]^T                    K=512 (NT)
// MODE 2: AV      C = attn[M,K] * values[K,N]                  K=2048 (NN)
// ---------------------------------------------------------------------------
static constexpr int KC = 32;
static constexpr int LDS_P = 36;     // NT pad (floats per row)
static constexpr int NN_P = 136;     // NN pad (floats per row)
static constexpr int A_FLOATS = 64 * LDS_P;              // 2304
static constexpr int B_FLOATS = 128 * LDS_P;             // 4608 (NN uses 32*136=4352 <= this)
static constexpr int STAGE_FLOATS = 2 * A_FLOATS + 2 * B_FLOATS;  // 13824
static constexpr int GEMM_SMEM = 2 * STAGE_FLOATS * 4;   // 110592 bytes

template <int MODE>
__global__ __launch_bounds__(256, 2) void k_gemm(const float* __restrict__ Ap,
                                                 const float* __restrict__ Bp,
                                                 float* __restrict__ Cp) {
    extern __shared__ float sm[];

    constexpr int KTOT = (MODE == 2) ? S : D;
    constexpr int NC = KTOT / KC;

    const int tid = threadIdx.x;
    const int n0 = blockIdx.x * 128;
    const int m0 = blockIdx.y * 64;
    const int bz = blockIdx.z;

    const float* Abase; size_t a_rs;
    const float* Bbase; size_t b_rs;
    float* Cbase; size_t c_rs;
    if (MODE == 0) {
        const int bb = m0 >> 10, t0 = m0 & 1023;
        Abase = Ap + ((size_t)t0 * B + bb) * D; a_rs = (size_t)B * D;
        Bbase = Bp + (size_t)n0 * D;            b_rs = D;
        Cbase = g_X + (size_t)m0 * D + n0;      c_rs = D;
    } else if (MODE == 1) {
        Abase = g_X + ((size_t)bz * T + m0) * D;     a_rs = D;
        Bbase = Bp + ((size_t)bz * S + n0) * D;      b_rs = D;
        Cbase = Cp + ((size_t)bz * T + m0) * S + n0; c_rs = S;
    } else {
        Abase = Ap + ((size_t)bz * T + m0) * S;      a_rs = S;
        Bbase = Bp + (size_t)bz * S * D + n0;        b_rs = D;   // values [S][D]
        Cbase = Cp + (size_t)m0 * B * D + (size_t)bz * D + n0; c_rs = (size_t)B * D;
    }

    const int lane = tid & 31, wid = tid >> 5;
    const int gr = lane >> 2, gc = lane & 3;
    const int m_w = (wid >> 2) * 32;   // warp m origin (2 m-groups)
    const int n_w = (wid & 3) * 32;    // warp n origin (4 n-groups)

    // Producer coords (NT): row = tid>>3, kq = (tid&7)*4
    const int prow = tid >> 3;
    const int pkq = (tid & 7) * 4;
    // Producer coords (NN B, MODE 2): row = tid>>5 (+8/pass), col = (tid&31)*4
    const int qrow = tid >> 5;
    const int qcol = (tid & 31) * 4;

    float4 na[2], nb[4];

    auto loadAB = [&](int c) {
        const int k0 = c * KC;
        #pragma unroll
        for (int j = 0; j < 2; j++) {
            const int row = prow + 32 * j;   // 0..63
            na[j] = *reinterpret_cast<const float4*>(Abase + (size_t)row * a_rs + k0 + pkq);
        }
        if (MODE != 2) {
            #pragma unroll
            for (int j = 0; j < 4; j++) {
                const int row = prow + 32 * j;  // 0..127
                nb[j] = *reinterpret_cast<const float4*>(Bbase + (size_t)row * b_rs + k0 + pkq);
            }
        } else {
            #pragma unroll
            for (int j = 0; j < 4; j++) {
                const int row = qrow + 8 * j;   // k index within chunk, 0..31
                nb[j] = *reinterpret_cast<const float4*>(Bbase + (size_t)(k0 + row) * b_rs + qcol);
            }
        }
    };
    auto stsAB = [&](int s) {
        float* sAh = sm + s * STAGE_FLOATS;
        float* sAl = sAh + A_FLOATS;
        float* sBh = sAl + A_FLOATS;
        float* sBl = sBh + B_FLOATS;
        #pragma unroll
        for (int j = 0; j < 2; j++) {
            const int off = (prow + 32 * j) * LDS_P + pkq;
            float4 v = na[j];
            float4 h, l;
            h.x = f2tf(v.x); l.x = f2tf(v.x - h.x);
            h.y = f2tf(v.y); l.y = f2tf(v.y - h.y);
            h.z = f2tf(v.z); l.z = f2tf(v.z - h.z);
            h.w = f2tf(v.w); l.w = f2tf(v.w - h.w);
            *reinterpret_cast<float4*>(sAh + off) = h;
            *reinterpret_cast<float4*>(sAl + off) = l;
        }
        #pragma unroll
        for (int j = 0; j < 4; j++) {
            const int off = (MODE != 2) ? (prow + 32 * j) * LDS_P + pkq
                                        : (qrow + 8 * j) * NN_P + qcol;
            float4 v = nb[j];
            float4 h, l;
            h.x = f2tf(v.x); l.x = f2tf(v.x - h.x);
            h.y = f2tf(v.y); l.y = f2tf(v.y - h.y);
            h.z = f2tf(v.z); l.z = f2tf(v.z - h.z);
            h.w = f2tf(v.w); l.w = f2tf(v.w - h.w);
            *reinterpret_cast<float4*>(sBh + off) = h;
            *reinterpret_cast<float4*>(sBl + off) = l;
        }
    };

    float acc[2][4][4];
    #pragma unroll
    for (int i = 0; i < 2; i++)
        #pragma unroll
        for (int j = 0; j < 4; j++)
            #pragma unroll
            for (int q = 0; q < 4; q++) acc[i][j][q] = 0.f;

    loadAB(0);
    stsAB(0);
    __syncthreads();

    for (int c = 0; c < NC; c++) {
        const int s = c & 1;
        if (c + 1 < NC) loadAB(c + 1);

        const float* sAh = sm + s * STAGE_FLOATS;
        const float* sAl = sAh + A_FLOATS;
        const float* sBh = sAl + A_FLOATS;
        const float* sBl = sBh + B_FLOATS;

        #pragma unroll
        for (int ks = 0; ks < 4; ks++) {
            uint32_t ah[2][4], al[2][4], bh[4][2], bl[4][2];
            #pragma unroll
            for (int mf = 0; mf < 2; mf++) {
                const int base = (m_w + mf * 16 + gr) * LDS_P + ks * 8 + gc;
                ah[mf][0] = __float_as_uint(sAh[base]);
                ah[mf][1] = __float_as_uint(sAh[base + 8 * LDS_P]);
                ah[mf][2] = __float_as_uint(sAh[base + 4]);
                ah[mf][3] = __float_as_uint(sAh[base + 8 * LDS_P + 4]);
                al[mf][0] = __float_as_uint(sAl[base]);
                al[mf][1] = __float_as_uint(sAl[base + 8 * LDS_P]);
                al[mf][2] = __float_as_uint(sAl[base + 4]);
                al[mf][3] = __float_as_uint(sAl[base + 8 * LDS_P + 4]);
            }
            #pragma unroll
            for (int nf = 0; nf < 4; nf++) {
                if (MODE != 2) {
                    const int base = (n_w + nf * 8 + gr) * LDS_P + ks * 8 + gc;
                    bh[nf][0] = __float_as_uint(sBh[base]);
                    bh[nf][1] = __float_as_uint(sBh[base + 4]);
                    bl[nf][0] = __float_as_uint(sBl[base]);
                    bl[nf][1] = __float_as_uint(sBl[base + 4]);
                } else {
                    const int base = (ks * 8 + gc) * NN_P + n_w + nf * 8 + gr;
                    bh[nf][0] = __float_as_uint(sBh[base]);
                    bh[nf][1] = __float_as_uint(sBh[base + 4 * NN_P]);
                    bl[nf][0] = __float_as_uint(sBl[base]);
                    bl[nf][1] = __float_as_uint(sBl[base + 4 * NN_P]);
                }
            }
            #pragma unroll
            for (int mf = 0; mf < 2; mf++)
                #pragma unroll
                for (int nf = 0; nf < 4; nf++) {
                    mma8(acc[mf][nf], ah[mf], bh[nf]);
                    mma8(acc[mf][nf], al[mf], bh[nf]);
                    mma8(acc[mf][nf], ah[mf], bl[nf]);
                }
        }
        if (c + 1 < NC) stsAB(s ^ 1);
        __syncthreads();
    }

    // Epilogue
    #pragma unroll
    for (int mf = 0; mf < 2; mf++)
        #pragma unroll
        for (int nf = 0; nf < 4; nf++) {
            const int mrow = m_w + mf * 16 + gr;
            const int ncol = n_w + nf * 8 + 2 * gc;
            float2 v0 = make_float2(acc[mf][nf][0], acc[mf][nf][1]);
            float2 v1 = make_float2(acc[mf][nf][2], acc[mf][nf][3]);
            *reinterpret_cast<float2*>(Cbase + (size_t)mrow * c_rs + ncol) = v0;
            *reinterpret_cast<float2*>(Cbase + (size_t)(mrow + 8) * c_rs + ncol) = v1;
        }
}

// ---------------------------------------------------------------------------
// LayerNorm in place on g_X rows (B*T rows of D)
// ---------------------------------------------------------------------------
__global__ __launch_bounds__(256) void k_ln(const float* __restrict__ gamma,
                                            const float* __restrict__ beta) {
    const int row = blockIdx.x;
    float* x = &g_X[(size_t)row * D];
    const int tid = threadIdx.x;

    float2 v = *reinterpret_cast<const float2*>(&x[tid * 2]);
    float s = v.x + v.y;
    float q = v.x * v.x + v.y * v.y;

    __shared__ float sh_s[8], sh_q[8];
    #pragma unroll
    for (int o = 16; o > 0; o >>= 1) {
        s += __shfl_xor_sync(0xffffffffu, s, o);
        q += __shfl_xor_sync(0xffffffffu, q, o);
    }
    if ((tid & 31) == 0) { sh_s[tid >> 5] = s; sh_q[tid >> 5] = q; }
    __syncthreads();
    float ts = 0.f, tq = 0.f;
    #pragma unroll
    for (int i = 0; i < 8; i++) { ts += sh_s[i]; tq += sh_q[i]; }

    const float mean = ts * (1.0f / D);
    const float var = tq * (1.0f / D) - mean * mean;
    const float rstd = rsqrtf(var + LN_EPS);

    float2 g = *reinterpret_cast<const float2*>(&gamma[tid * 2]);
    float2 bb = *reinterpret_cast<const float2*>(&beta[tid * 2]);
    float2 o;
    o.x = g.x * (v.x - mean) * rstd + bb.x;
    o.y = g.y * (v.y - mean) * rstd + bb.y;
    *reinterpret_cast<float2*>(&x[tid * 2]) = o;
}

// ---------------------------------------------------------------------------
// Softmax over S for each of B*T rows, in place
// ---------------------------------------------------------------------------
__global__ __launch_bounds__(256) void k_softmax(float* __restrict__ attn) {
    const size_t row = blockIdx.x;
    float* p = attn + row * (size_t)S;
    const int tid = threadIdx.x;

    float4 v0 = reinterpret_cast<const float4*>(p)[tid * 2 + 0];
    float4 v1 = reinterpret_cast<const float4*>(p)[tid * 2 + 1];

    float m = fmaxf(fmaxf(fmaxf(v0.x, v0.y), fmaxf(v0.z, v0.w)),
                    fmaxf(fmaxf(v1.x, v1.y), fmaxf(v1.z, v1.w)));
    __shared__ float sh[8];
    #pragma unroll
    for (int o = 16; o > 0; o >>= 1) m = fmaxf(m, __shfl_xor_sync(0xffffffffu, m, o));
    if ((tid & 31) == 0) sh[tid >> 5] = m;
    __syncthreads();
    float gm = sh[0];
    #pragma unroll
    for (int i = 1; i < 8; i++) gm = fmaxf(gm, sh[i]);
    __syncthreads();

    v0.x = __expf(v0.x - gm); v0.y = __expf(v0.y - gm);
    v0.z = __expf(v0.z - gm); v0.w = __expf(v0.w - gm);
    v1.x = __expf(v1.x - gm); v1.y = __expf(v1.y - gm);
    v1.z = __expf(v1.z - gm); v1.w = __expf(v1.w - gm);

    float s = v0.x + v0.y + v0.z + v0.w + v1.x + v1.y + v1.z + v1.w;
    #pragma unroll
    for (int o = 16; o > 0; o >>= 1) s += __shfl_xor_sync(0xffffffffu, s, o);
    if ((tid & 31) == 0) sh[tid >> 5] = s;
    __syncthreads();
    float gs = 0.f;
    #pragma unroll
    for (int i = 0; i < 8; i++) gs += sh[i];
    const float inv = 1.0f / gs;

    v0.x *= inv; v0.y *= inv; v0.z *= inv; v0.w *= inv;
    v1.x *= inv; v1.y *= inv; v1.z *= inv; v1.w *= inv;
    reinterpret_cast<float4*>(p)[tid * 2 + 0] = v0;
    reinterpret_cast<float4*>(p)[tid * 2 + 1] = v1;
}

// ---------------------------------------------------------------------------
extern "C" void kernel_launch(void* const* d_in, const int* in_sizes, int n_in,
                              void* d_out, int out_size) {
    const float* inp    = (const float*)d_in[0];  // [T,B,D]
    const float* ctx    = (const float*)d_in[1];  // [B,S,D]
    const float* values = (const float*)d_in[2];  // [B,S,D]
    const float* W      = (const float*)d_in[3];  // [D,D]
    const float* gamma  = (const float*)d_in[4];  // [D]
    const float* beta   = (const float*)d_in[5];  // [D]

    float* out_wc   = (float*)d_out;                       // [T,B,D]
    float* out_attn = (float*)d_out + (size_t)T * B * D;   // [B*T,S]

    cudaFuncSetAttribute(k_gemm<0>, cudaFuncAttributeMaxDynamicSharedMemorySize, GEMM_SMEM);
    cudaFuncSetAttribute(k_gemm<1>, cudaFuncAttributeMaxDynamicSharedMemorySize, GEMM_SMEM);
    cudaFuncSetAttribute(k_gemm<2>, cudaFuncAttributeMaxDynamicSharedMemorySize, GEMM_SMEM);

    // 1) linear: g_X = inp @ W^T (rows b*T+t)
    {
        dim3 grid(D / 128, (B * T) / 64, 1);
        k_gemm<0><<<grid, 256, GEMM_SMEM>>>(inp, W, nullptr);
    }
    // 2) LayerNorm in place
    k_ln<<<B * T, 256>>>(gamma, beta);
    // 3) scores -> attn region
    {
        dim3 grid(S / 128, T / 64, B);
        k_gemm<1><<<grid, 256, GEMM_SMEM>>>(nullptr, ctx, out_attn);
    }
    // 4) softmax in place
    k_softmax<<<B * T, 256>>>(out_attn);
    // 5) weightedContext (NN: B = values directly)
    {
        dim3 grid(D / 128, T / 64, B);
        k_gemm<2><<<grid, 256, GEMM_SMEM>>>(out_attn, values, out_wc);
    }
}

// round 7
// speedup vs baseline: 1.6817x; 1.0423x over previous
#include <cuda_runtime.h>
#include <cstdint>

// Problem dims (fixed)
static constexpr int T = 1024, B = 32, S = 2048, D = 512;
static constexpr float LN_EPS = 1e-6f;

// Scratch: linear+LN output [B][T][D]
__device__ __align__(256) float g_X[(size_t)B * T * D];

// ---------------------------------------------------------------------------
__device__ __forceinline__ float f2tf(float x) {
    uint32_t r; asm("cvt.rna.tf32.f32 %0, %1;" : "=r"(r) : "f"(x));
    return __uint_as_float(r);
}
__device__ __forceinline__ void mma8(float* d, const uint32_t* a, const uint32_t* b) {
    asm volatile(
        "mma.sync.aligned.m16n8k8.row.col.f32.tf32.tf32.f32 "
        "{%0,%1,%2,%3}, {%4,%5,%6,%7}, {%8,%9}, {%0,%1,%2,%3};"
        : "+f"(d[0]), "+f"(d[1]), "+f"(d[2]), "+f"(d[3])
        : "r"(a[0]), "r"(a[1]), "r"(a[2]), "r"(a[3]), "r"(b[0]), "r"(b[1]));
}

// ---------------------------------------------------------------------------
// Split-TF32 GEMM, CTA tile 128x128, KC=32, double-buffered smem.
// Split-MMA passes issued breadth-first (all hh, all lh, all hl) so
// consecutive MMAs never share an accumulator (no RAW stalls).
// MODE 0: linear  C[M,N] = inp(row b*T+t)[M,K] * W[N,K]^T      K=512 (NT)
// MODE 1: scores  C = g_X[M,K] * ctx[N,K]^T                    K=512 (NT)
// MODE 2: AV      C = attn[M,K] * values[K,N]                  K=2048 (NN)
// 256 threads: 8 warps (2x4), warp tile 64x32.
// ---------------------------------------------------------------------------
static constexpr int KC = 32;
static constexpr int LDS_P = 36;     // NT pad (floats per row)
static constexpr int NN_P = 136;     // NN pad (floats per row)
static constexpr int REG_FLOATS = 128 * LDS_P;          // 4608 floats per region
static constexpr int STAGE_FLOATS = 4 * REG_FLOATS;     // Ah, Al, Bh, Bl
static constexpr int GEMM_SMEM = 2 * STAGE_FLOATS * 4;  // 147456 bytes

template <int MODE>
__global__ __launch_bounds__(256) void k_gemm(const float* __restrict__ Ap,
                                              const float* __restrict__ Bp,
                                              float* __restrict__ Cp) {
    extern __shared__ float sm[];

    constexpr int KTOT = (MODE == 2) ? S : D;
    constexpr int NC = KTOT / KC;

    const int tid = threadIdx.x;
    const int n0 = blockIdx.x * 128;
    const int m0 = blockIdx.y * 128;
    const int bz = blockIdx.z;

    const float* Abase; size_t a_rs;
    const float* Bbase; size_t b_rs;
    float* Cbase; size_t c_rs;
    if (MODE == 0) {
        const int bb = m0 >> 10, t0 = m0 & 1023;
        Abase = Ap + ((size_t)t0 * B + bb) * D; a_rs = (size_t)B * D;
        Bbase = Bp + (size_t)n0 * D;            b_rs = D;
        Cbase = g_X + (size_t)m0 * D + n0;      c_rs = D;
    } else if (MODE == 1) {
        Abase = g_X + ((size_t)bz * T + m0) * D;     a_rs = D;
        Bbase = Bp + ((size_t)bz * S + n0) * D;      b_rs = D;
        Cbase = Cp + ((size_t)bz * T + m0) * S + n0; c_rs = S;
    } else {
        Abase = Ap + ((size_t)bz * T + m0) * S;      a_rs = S;
        Bbase = Bp + (size_t)bz * S * D + n0;        b_rs = D;   // values [S][D]
        Cbase = Cp + (size_t)m0 * B * D + (size_t)bz * D + n0; c_rs = (size_t)B * D;
    }

    const int lane = tid & 31, wid = tid >> 5;
    const int gr = lane >> 2, gc = lane & 3;
    const int m_w = (wid >> 2) * 64;   // warp m origin
    const int n_w = (wid & 3) * 32;    // warp n origin

    // Producer coords (NT): row = tid>>3 (+32/pass), kq = (tid&7)*4
    const int prow = tid >> 3;
    const int pkq = (tid & 7) * 4;
    // Producer coords (NN B operand, MODE 2): row = tid>>5 (+8/pass), col = (tid&31)*4
    const int qrow = tid >> 5;
    const int qcol = (tid & 31) * 4;

    float4 na[4], nb[4];

    auto loadAB = [&](int c) {
        const int k0 = c * KC;
        #pragma unroll
        for (int j = 0; j < 4; j++) {
            const int row = prow + 32 * j;
            na[j] = *reinterpret_cast<const float4*>(Abase + (size_t)row * a_rs + k0 + pkq);
        }
        if (MODE != 2) {
            #pragma unroll
            for (int j = 0; j < 4; j++) {
                const int row = prow + 32 * j;
                nb[j] = *reinterpret_cast<const float4*>(Bbase + (size_t)row * b_rs + k0 + pkq);
            }
        } else {
            #pragma unroll
            for (int j = 0; j < 4; j++) {
                const int row = qrow + 8 * j;   // k index within chunk
                nb[j] = *reinterpret_cast<const float4*>(Bbase + (size_t)(k0 + row) * b_rs + qcol);
            }
        }
    };
    auto stsAB = [&](int s) {
        float* sAh = sm + s * STAGE_FLOATS;
        float* sAl = sAh + REG_FLOATS;
        float* sBh = sAl + REG_FLOATS;
        float* sBl = sBh + REG_FLOATS;
        #pragma unroll
        for (int j = 0; j < 4; j++) {
            const int off = (prow + 32 * j) * LDS_P + pkq;
            float4 v = na[j];
            float4 h, l;
            h.x = f2tf(v.x); l.x = f2tf(v.x - h.x);
            h.y = f2tf(v.y); l.y = f2tf(v.y - h.y);
            h.z = f2tf(v.z); l.z = f2tf(v.z - h.z);
            h.w = f2tf(v.w); l.w = f2tf(v.w - h.w);
            *reinterpret_cast<float4*>(sAh + off) = h;
            *reinterpret_cast<float4*>(sAl + off) = l;
        }
        #pragma unroll
        for (int j = 0; j < 4; j++) {
            const int off = (MODE != 2) ? (prow + 32 * j) * LDS_P + pkq
                                        : (qrow + 8 * j) * NN_P + qcol;
            float4 v = nb[j];
            float4 h, l;
            h.x = f2tf(v.x); l.x = f2tf(v.x - h.x);
            h.y = f2tf(v.y); l.y = f2tf(v.y - h.y);
            h.z = f2tf(v.z); l.z = f2tf(v.z - h.z);
            h.w = f2tf(v.w); l.w = f2tf(v.w - h.w);
            *reinterpret_cast<float4*>(sBh + off) = h;
            *reinterpret_cast<float4*>(sBl + off) = l;
        }
    };

    float acc[4][4][4];
    #pragma unroll
    for (int i = 0; i < 4; i++)
        #pragma unroll
        for (int j = 0; j < 4; j++)
            #pragma unroll
            for (int q = 0; q < 4; q++) acc[i][j][q] = 0.f;

    loadAB(0);
    stsAB(0);
    __syncthreads();

    for (int c = 0; c < NC; c++) {
        const int s = c & 1;
        if (c + 1 < NC) loadAB(c + 1);

        const float* sAh = sm + s * STAGE_FLOATS;
        const float* sAl = sAh + REG_FLOATS;
        const float* sBh = sAl + REG_FLOATS;
        const float* sBl = sBh + REG_FLOATS;

        #pragma unroll
        for (int ks = 0; ks < 4; ks++) {
            uint32_t ah[4][4], al[4][4], bh[4][2], bl[4][2];
            #pragma unroll
            for (int mf = 0; mf < 4; mf++) {
                const int base = (m_w + mf * 16 + gr) * LDS_P + ks * 8 + gc;
                ah[mf][0] = __float_as_uint(sAh[base]);
                ah[mf][1] = __float_as_uint(sAh[base + 8 * LDS_P]);
                ah[mf][2] = __float_as_uint(sAh[base + 4]);
                ah[mf][3] = __float_as_uint(sAh[base + 8 * LDS_P + 4]);
                al[mf][0] = __float_as_uint(sAl[base]);
                al[mf][1] = __float_as_uint(sAl[base + 8 * LDS_P]);
                al[mf][2] = __float_as_uint(sAl[base + 4]);
                al[mf][3] = __float_as_uint(sAl[base + 8 * LDS_P + 4]);
            }
            #pragma unroll
            for (int nf = 0; nf < 4; nf++) {
                if (MODE != 2) {
                    const int base = (n_w + nf * 8 + gr) * LDS_P + ks * 8 + gc;
                    bh[nf][0] = __float_as_uint(sBh[base]);
                    bh[nf][1] = __float_as_uint(sBh[base + 4]);
                    bl[nf][0] = __float_as_uint(sBl[base]);
                    bl[nf][1] = __float_as_uint(sBl[base + 4]);
                } else {
                    const int base = (ks * 8 + gc) * NN_P + n_w + nf * 8 + gr;
                    bh[nf][0] = __float_as_uint(sBh[base]);
                    bh[nf][1] = __float_as_uint(sBh[base + 4 * NN_P]);
                    bl[nf][0] = __float_as_uint(sBl[base]);
                    bl[nf][1] = __float_as_uint(sBl[base + 4 * NN_P]);
                }
            }
            // Breadth-first split passes: consecutive MMAs never share an
            // accumulator -> no RAW stalls on the tensor pipe.
            #pragma unroll
            for (int mf = 0; mf < 4; mf++)
                #pragma unroll
                for (int nf = 0; nf < 4; nf++)
                    mma8(acc[mf][nf], ah[mf], bh[nf]);
            #pragma unroll
            for (int mf = 0; mf < 4; mf++)
                #pragma unroll
                for (int nf = 0; nf < 4; nf++)
                    mma8(acc[mf][nf], al[mf], bh[nf]);
            #pragma unroll
            for (int mf = 0; mf < 4; mf++)
                #pragma unroll
                for (int nf = 0; nf < 4; nf++)
                    mma8(acc[mf][nf], ah[mf], bl[nf]);
        }
        if (c + 1 < NC) stsAB(s ^ 1);
        __syncthreads();
    }

    // Epilogue
    #pragma unroll
    for (int mf = 0; mf < 4; mf++)
        #pragma unroll
        for (int nf = 0; nf < 4; nf++) {
            const int mrow = m_w + mf * 16 + gr;
            const int ncol = n_w + nf * 8 + 2 * gc;
            float2 v0 = make_float2(acc[mf][nf][0], acc[mf][nf][1]);
            float2 v1 = make_float2(acc[mf][nf][2], acc[mf][nf][3]);
            *reinterpret_cast<float2*>(Cbase + (size_t)mrow * c_rs + ncol) = v0;
            *reinterpret_cast<float2*>(Cbase + (size_t)(mrow + 8) * c_rs + ncol) = v1;
        }
}

// ---------------------------------------------------------------------------
// LayerNorm in place on g_X rows (B*T rows of D)
// ---------------------------------------------------------------------------
__global__ __launch_bounds__(256) void k_ln(const float* __restrict__ gamma,
                                            const float* __restrict__ beta) {
    const int row = blockIdx.x;
    float* x = &g_X[(size_t)row * D];
    const int tid = threadIdx.x;

    float2 v = *reinterpret_cast<const float2*>(&x[tid * 2]);
    float s = v.x + v.y;
    float q = v.x * v.x + v.y * v.y;

    __shared__ float sh_s[8], sh_q[8];
    #pragma unroll
    for (int o = 16; o > 0; o >>= 1) {
        s += __shfl_xor_sync(0xffffffffu, s, o);
        q += __shfl_xor_sync(0xffffffffu, q, o);
    }
    if ((tid & 31) == 0) { sh_s[tid >> 5] = s; sh_q[tid >> 5] = q; }
    __syncthreads();
    float ts = 0.f, tq = 0.f;
    #pragma unroll
    for (int i = 0; i < 8; i++) { ts += sh_s[i]; tq += sh_q[i]; }

    const float mean = ts * (1.0f / D);
    const float var = tq * (1.0f / D) - mean * mean;
    const float rstd = rsqrtf(var + LN_EPS);

    float2 g = *reinterpret_cast<const float2*>(&gamma[tid * 2]);
    float2 bb = *reinterpret_cast<const float2*>(&beta[tid * 2]);
    float2 o;
    o.x = g.x * (v.x - mean) * rstd + bb.x;
    o.y = g.y * (v.y - mean) * rstd + bb.y;
    *reinterpret_cast<float2*>(&x[tid * 2]) = o;
}

// ---------------------------------------------------------------------------
// Softmax over S for each of B*T rows, in place
// ---------------------------------------------------------------------------
__global__ __launch_bounds__(256) void k_softmax(float* __restrict__ attn) {
    const size_t row = blockIdx.x;
    float* p = attn + row * (size_t)S;
    const int tid = threadIdx.x;

    float4 v0 = reinterpret_cast<const float4*>(p)[tid * 2 + 0];
    float4 v1 = reinterpret_cast<const float4*>(p)[tid * 2 + 1];

    float m = fmaxf(fmaxf(fmaxf(v0.x, v0.y), fmaxf(v0.z, v0.w)),
                    fmaxf(fmaxf(v1.x, v1.y), fmaxf(v1.z, v1.w)));
    __shared__ float sh[8];
    #pragma unroll
    for (int o = 16; o > 0; o >>= 1) m = fmaxf(m, __shfl_xor_sync(0xffffffffu, m, o));
    if ((tid & 31) == 0) sh[tid >> 5] = m;
    __syncthreads();
    float gm = sh[0];
    #pragma unroll
    for (int i = 1; i < 8; i++) gm = fmaxf(gm, sh[i]);
    __syncthreads();

    v0.x = __expf(v0.x - gm); v0.y = __expf(v0.y - gm);
    v0.z = __expf(v0.z - gm); v0.w = __expf(v0.w - gm);
    v1.x = __expf(v1.x - gm); v1.y = __expf(v1.y - gm);
    v1.z = __expf(v1.z - gm); v1.w = __expf(v1.w - gm);

    float s = v0.x + v0.y + v0.z + v0.w + v1.x + v1.y + v1.z + v1.w;
    #pragma unroll
    for (int o = 16; o > 0; o >>= 1) s += __shfl_xor_sync(0xffffffffu, s, o);
    if ((tid & 31) == 0) sh[tid >> 5] = s;
    __syncthreads();
    float gs = 0.f;
    #pragma unroll
    for (int i = 0; i < 8; i++) gs += sh[i];
    const float inv = 1.0f / gs;

    v0.x *= inv; v0.y *= inv; v0.z *= inv; v0.w *= inv;
    v1.x *= inv; v1.y *= inv; v1.z *= inv; v1.w *= inv;
    reinterpret_cast<float4*>(p)[tid * 2 + 0] = v0;
    reinterpret_cast<float4*>(p)[tid * 2 + 1] = v1;
}

// ---------------------------------------------------------------------------
extern "C" void kernel_launch(void* const* d_in, const int* in_sizes, int n_in,
                              void* d_out, int out_size) {
    const float* inp    = (const float*)d_in[0];  // [T,B,D]
    const float* ctx    = (const float*)d_in[1];  // [B,S,D]
    const float* values = (const float*)d_in[2];  // [B,S,D]
    const float* W      = (const float*)d_in[3];  // [D,D]
    const float* gamma  = (const float*)d_in[4];  // [D]
    const float* beta   = (const float*)d_in[5];  // [D]

    float* out_wc   = (float*)d_out;                       // [T,B,D]
    float* out_attn = (float*)d_out + (size_t)T * B * D;   // [B*T,S]

    cudaFuncSetAttribute(k_gemm<0>, cudaFuncAttributeMaxDynamicSharedMemorySize, GEMM_SMEM);
    cudaFuncSetAttribute(k_gemm<1>, cudaFuncAttributeMaxDynamicSharedMemorySize, GEMM_SMEM);
    cudaFuncSetAttribute(k_gemm<2>, cudaFuncAttributeMaxDynamicSharedMemorySize, GEMM_SMEM);

    // 1) linear: g_X = inp @ W^T (rows b*T+t)
    {
        dim3 grid(D / 128, (B * T) / 128, 1);
        k_gemm<0><<<grid, 256, GEMM_SMEM>>>(inp, W, nullptr);
    }
    // 2) LayerNorm in place
    k_ln<<<B * T, 256>>>(gamma, beta);
    // 3) scores -> attn region
    {
        dim3 grid(S / 128, T / 128, B);
        k_gemm<1><<<grid, 256, GEMM_SMEM>>>(nullptr, ctx, out_attn);
    }
    // 4) softmax in place
    k_softmax<<<B * T, 256>>>(out_attn);
    // 5) weightedContext (NN: B = values directly)
    {
        dim3 grid(D / 128, T / 128, B);
        k_gemm<2><<<grid, 256, GEMM_SMEM>>>(out_attn, values, out_wc);
    }
}

// round 8
// speedup vs baseline: 1.9120x; 1.1370x over previous
#include <cuda_runtime.h>
#include <cuda_bf16.h>
#include <cstdint>

// Problem dims (fixed)
static constexpr int T = 1024, B = 32, S = 2048, D = 512;
static constexpr float LN_EPS = 1e-6f;

// Scratch: linear+LN output [B][T][D]
__device__ __align__(256) float g_X[(size_t)B * T * D];

// ---------------------------------------------------------------------------
__device__ __forceinline__ float f2tf(float x) {
    uint32_t r; asm("cvt.rna.tf32.f32 %0, %1;" : "=r"(r) : "f"(x));
    return __uint_as_float(r);
}
__device__ __forceinline__ void mma8(float* d, const uint32_t* a, const uint32_t* b) {
    asm volatile(
        "mma.sync.aligned.m16n8k8.row.col.f32.tf32.tf32.f32 "
        "{%0,%1,%2,%3}, {%4,%5,%6,%7}, {%8,%9}, {%0,%1,%2,%3};"
        : "+f"(d[0]), "+f"(d[1]), "+f"(d[2]), "+f"(d[3])
        : "r"(a[0]), "r"(a[1]), "r"(a[2]), "r"(a[3]), "r"(b[0]), "r"(b[1]));
}
__device__ __forceinline__ void mma16(float* d, const uint32_t* a, const uint32_t* b) {
    asm volatile(
        "mma.sync.aligned.m16n8k16.row.col.f32.bf16.bf16.f32 "
        "{%0,%1,%2,%3}, {%4,%5,%6,%7}, {%8,%9}, {%0,%1,%2,%3};"
        : "+f"(d[0]), "+f"(d[1]), "+f"(d[2]), "+f"(d[3])
        : "r"(a[0]), "r"(a[1]), "r"(a[2]), "r"(a[3]), "r"(b[0]), "r"(b[1]));
}

// ---------------------------------------------------------------------------
// Split-TF32 GEMM (modes 0,1), CTA tile 128x128, KC=32, double-buffered.
// MODE 0: linear  C[M,N] = inp(row b*T+t)[M,K] * W[N,K]^T      K=512 (NT)
// MODE 1: scores  C = g_X[M,K] * ctx[N,K]^T                    K=512 (NT)
// 256 threads: 8 warps (2x4), warp tile 64x32.
// ---------------------------------------------------------------------------
static constexpr int KC = 32;
static constexpr int LDS_P = 36;
static constexpr int REG_FLOATS = 128 * LDS_P;          // 4608
static constexpr int STAGE_FLOATS = 4 * REG_FLOATS;     // Ah, Al, Bh, Bl
static constexpr int GEMM_SMEM = 2 * STAGE_FLOATS * 4;  // 147456 bytes

template <int MODE>
__global__ __launch_bounds__(256) void k_gemm(const float* __restrict__ Ap,
                                              const float* __restrict__ Bp,
                                              float* __restrict__ Cp) {
    extern __shared__ float sm[];
    constexpr int NC = D / KC;

    const int tid = threadIdx.x;
    const int n0 = blockIdx.x * 128;
    const int m0 = blockIdx.y * 128;
    const int bz = blockIdx.z;

    const float* Abase; size_t a_rs;
    const float* Bbase; size_t b_rs;
    float* Cbase; size_t c_rs;
    if (MODE == 0) {
        const int bb = m0 >> 10, t0 = m0 & 1023;
        Abase = Ap + ((size_t)t0 * B + bb) * D; a_rs = (size_t)B * D;
        Bbase = Bp + (size_t)n0 * D;            b_rs = D;
        Cbase = g_X + (size_t)m0 * D + n0;      c_rs = D;
    } else {
        Abase = g_X + ((size_t)bz * T + m0) * D;     a_rs = D;
        Bbase = Bp + ((size_t)bz * S + n0) * D;      b_rs = D;
        Cbase = Cp + ((size_t)bz * T + m0) * S + n0; c_rs = S;
    }

    const int lane = tid & 31, wid = tid >> 5;
    const int gr = lane >> 2, gc = lane & 3;
    const int m_w = (wid >> 2) * 64;
    const int n_w = (wid & 3) * 32;

    const int prow = tid >> 3;
    const int pkq = (tid & 7) * 4;

    float4 na[4], nb[4];

    auto loadAB = [&](int c) {
        const int k0 = c * KC;
        #pragma unroll
        for (int j = 0; j < 4; j++) {
            const int row = prow + 32 * j;
            na[j] = *reinterpret_cast<const float4*>(Abase + (size_t)row * a_rs + k0 + pkq);
            nb[j] = *reinterpret_cast<const float4*>(Bbase + (size_t)row * b_rs + k0 + pkq);
        }
    };
    auto stsAB = [&](int s) {
        float* sAh = sm + s * STAGE_FLOATS;
        float* sAl = sAh + REG_FLOATS;
        float* sBh = sAl + REG_FLOATS;
        float* sBl = sBh + REG_FLOATS;
        #pragma unroll
        for (int j = 0; j < 4; j++) {
            const int off = (prow + 32 * j) * LDS_P + pkq;
            float4 v = na[j];
            float4 h, l;
            h.x = f2tf(v.x); l.x = f2tf(v.x - h.x);
            h.y = f2tf(v.y); l.y = f2tf(v.y - h.y);
            h.z = f2tf(v.z); l.z = f2tf(v.z - h.z);
            h.w = f2tf(v.w); l.w = f2tf(v.w - h.w);
            *reinterpret_cast<float4*>(sAh + off) = h;
            *reinterpret_cast<float4*>(sAl + off) = l;
            v = nb[j];
            h.x = f2tf(v.x); l.x = f2tf(v.x - h.x);
            h.y = f2tf(v.y); l.y = f2tf(v.y - h.y);
            h.z = f2tf(v.z); l.z = f2tf(v.z - h.z);
            h.w = f2tf(v.w); l.w = f2tf(v.w - h.w);
            *reinterpret_cast<float4*>(sBh + off) = h;
            *reinterpret_cast<float4*>(sBl + off) = l;
        }
    };

    float acc[4][4][4];
    #pragma unroll
    for (int i = 0; i < 4; i++)
        #pragma unroll
        for (int j = 0; j < 4; j++)
            #pragma unroll
            for (int q = 0; q < 4; q++) acc[i][j][q] = 0.f;

    loadAB(0);
    stsAB(0);
    __syncthreads();

    for (int c = 0; c < NC; c++) {
        const int s = c & 1;
        if (c + 1 < NC) loadAB(c + 1);

        const float* sAh = sm + s * STAGE_FLOATS;
        const float* sAl = sAh + REG_FLOATS;
        const float* sBh = sAl + REG_FLOATS;
        const float* sBl = sBh + REG_FLOATS;

        #pragma unroll
        for (int ks = 0; ks < 4; ks++) {
            uint32_t ah[4][4], al[4][4], bh[4][2], bl[4][2];
            #pragma unroll
            for (int mf = 0; mf < 4; mf++) {
                const int base = (m_w + mf * 16 + gr) * LDS_P + ks * 8 + gc;
                ah[mf][0] = __float_as_uint(sAh[base]);
                ah[mf][1] = __float_as_uint(sAh[base + 8 * LDS_P]);
                ah[mf][2] = __float_as_uint(sAh[base + 4]);
                ah[mf][3] = __float_as_uint(sAh[base + 8 * LDS_P + 4]);
                al[mf][0] = __float_as_uint(sAl[base]);
                al[mf][1] = __float_as_uint(sAl[base + 8 * LDS_P]);
                al[mf][2] = __float_as_uint(sAl[base + 4]);
                al[mf][3] = __float_as_uint(sAl[base + 8 * LDS_P + 4]);
            }
            #pragma unroll
            for (int nf = 0; nf < 4; nf++) {
                const int base = (n_w + nf * 8 + gr) * LDS_P + ks * 8 + gc;
                bh[nf][0] = __float_as_uint(sBh[base]);
                bh[nf][1] = __float_as_uint(sBh[base + 4]);
                bl[nf][0] = __float_as_uint(sBl[base]);
                bl[nf][1] = __float_as_uint(sBl[base + 4]);
            }
            #pragma unroll
            for (int mf = 0; mf < 4; mf++)
                #pragma unroll
                for (int nf = 0; nf < 4; nf++)
                    mma8(acc[mf][nf], ah[mf], bh[nf]);
            #pragma unroll
            for (int mf = 0; mf < 4; mf++)
                #pragma unroll
                for (int nf = 0; nf < 4; nf++)
                    mma8(acc[mf][nf], al[mf], bh[nf]);
            #pragma unroll
            for (int mf = 0; mf < 4; mf++)
                #pragma unroll
                for (int nf = 0; nf < 4; nf++)
                    mma8(acc[mf][nf], ah[mf], bl[nf]);
        }
        if (c + 1 < NC) stsAB(s ^ 1);
        __syncthreads();
    }

    #pragma unroll
    for (int mf = 0; mf < 4; mf++)
        #pragma unroll
        for (int nf = 0; nf < 4; nf++) {
            const int mrow = m_w + mf * 16 + gr;
            const int ncol = n_w + nf * 8 + 2 * gc;
            float2 v0 = make_float2(acc[mf][nf][0], acc[mf][nf][1]);
            float2 v1 = make_float2(acc[mf][nf][2], acc[mf][nf][3]);
            *reinterpret_cast<float2*>(Cbase + (size_t)mrow * c_rs + ncol) = v0;
            *reinterpret_cast<float2*>(Cbase + (size_t)(mrow + 8) * c_rs + ncol) = v1;
        }
}

// ---------------------------------------------------------------------------
// AV GEMM in split-BF16 (bf16x3): out[t][b][d] = sum_s attn[b][t][s]*values[b][s][d]
// CTA tile 128(M)x128(N), KC=32, double-buffered, 256 threads, warp tile 64x32.
// mma.m16n8k16.bf16: K=16 per MMA -> half the instructions of tf32 k8.
// A (attn) smem: bf16 [m][k], row pad 40 halves.
// B (values) smem: bf16 k-pair interleaved [kp][n][2], row pad 272 halves.
// ---------------------------------------------------------------------------
static constexpr int AV_A_PAD = 40;                       // halves per A row
static constexpr int AV_A_HALVES = 128 * AV_A_PAD;        // 5120
static constexpr int AV_B_PAD = 272;                      // halves per kp row
static constexpr int AV_B_HALVES = 16 * AV_B_PAD;         // 4352
static constexpr int AV_STAGE_HALVES = 2 * AV_A_HALVES + 2 * AV_B_HALVES;  // 18944
static constexpr int AV_SMEM = 2 * AV_STAGE_HALVES * 2;   // 75776 bytes

__global__ __launch_bounds__(256) void k_gemm_av(const float* __restrict__ attn,
                                                 const float* __restrict__ values,
                                                 float* __restrict__ out) {
    extern __shared__ __nv_bfloat16 smh[];
    constexpr int NC = S / KC;   // 64

    const int tid = threadIdx.x;
    const int n0 = blockIdx.x * 128;
    const int m0 = blockIdx.y * 128;
    const int bz = blockIdx.z;

    const float* Abase = attn + ((size_t)bz * T + m0) * S;
    const float* Bbase = values + (size_t)bz * S * D + n0;
    float* Cbase = out + (size_t)m0 * B * D + (size_t)bz * D + n0;
    const size_t c_rs = (size_t)B * D;

    const int lane = tid & 31, wid = tid >> 5;
    const int gr = lane >> 2, gc = lane & 3;
    const int m_w = (wid >> 2) * 64;
    const int n_w = (wid & 3) * 32;

    // A producer: row = tid>>3 (+32/pass), k = (tid&7)*4 .. +3
    const int prow = tid >> 3;
    const int pkq = (tid & 7) * 4;
    // B producer: k = tid>>5 (+8/pass), n = (tid&31)*4 .. +3
    const int qrow = tid >> 5;
    const int qcol = (tid & 31) * 4;

    float4 na[4], nb[4];

    auto loadAB = [&](int c) {
        const int k0 = c * KC;
        #pragma unroll
        for (int j = 0; j < 4; j++) {
            na[j] = *reinterpret_cast<const float4*>(Abase + (size_t)(prow + 32 * j) * S + k0 + pkq);
            nb[j] = *reinterpret_cast<const float4*>(Bbase + (size_t)(k0 + qrow + 8 * j) * D + qcol);
        }
    };
    auto stsAB = [&](int s) {
        __nv_bfloat16* sAh = smh + s * AV_STAGE_HALVES;
        __nv_bfloat16* sAl = sAh + AV_A_HALVES;
        __nv_bfloat16* sBh = sAl + AV_A_HALVES;
        __nv_bfloat16* sBl = sBh + AV_B_HALVES;
        #pragma unroll
        for (int j = 0; j < 4; j++) {
            // A: 4 consecutive halves at [row][pkq]
            const int off = (prow + 32 * j) * AV_A_PAD + pkq;
            const float4 v = na[j];
            __nv_bfloat16 h0 = __float2bfloat16(v.x);
            __nv_bfloat16 h1 = __float2bfloat16(v.y);
            __nv_bfloat16 h2 = __float2bfloat16(v.z);
            __nv_bfloat16 h3 = __float2bfloat16(v.w);
            __nv_bfloat162 hp0 = {h0, h1}, hp1 = {h2, h3};
            __nv_bfloat162 lp0 = {__float2bfloat16(v.x - __bfloat162float(h0)),
                                  __float2bfloat16(v.y - __bfloat162float(h1))};
            __nv_bfloat162 lp1 = {__float2bfloat16(v.z - __bfloat162float(h2)),
                                  __float2bfloat16(v.w - __bfloat162float(h3))};
            *reinterpret_cast<__nv_bfloat162*>(sAh + off) = hp0;
            *reinterpret_cast<__nv_bfloat162*>(sAh + off + 2) = hp1;
            *reinterpret_cast<__nv_bfloat162*>(sAl + off) = lp0;
            *reinterpret_cast<__nv_bfloat162*>(sAl + off + 2) = lp1;
        }
        #pragma unroll
        for (int j = 0; j < 4; j++) {
            // B: k = qrow+8j, scattered halves at [kp][n][slot]
            const int kk = qrow + 8 * j;
            const int kp = kk >> 1, slot = kk & 1;
            const int base = kp * AV_B_PAD + qcol * 2 + slot;
            const float4 v = nb[j];
            const float vv[4] = {v.x, v.y, v.z, v.w};
            #pragma unroll
            for (int i = 0; i < 4; i++) {
                __nv_bfloat16 h = __float2bfloat16(vv[i]);
                sBh[base + i * 2] = h;
                sBl[base + i * 2] = __float2bfloat16(vv[i] - __bfloat162float(h));
            }
        }
    };

    float acc[4][4][4];
    #pragma unroll
    for (int i = 0; i < 4; i++)
        #pragma unroll
        for (int j = 0; j < 4; j++)
            #pragma unroll
            for (int q = 0; q < 4; q++) acc[i][j][q] = 0.f;

    loadAB(0);
    stsAB(0);
    __syncthreads();

    for (int c = 0; c < NC; c++) {
        const int s = c & 1;
        if (c + 1 < NC) loadAB(c + 1);

        const __nv_bfloat16* sAh = smh + s * AV_STAGE_HALVES;
        const __nv_bfloat16* sAl = sAh + AV_A_HALVES;
        const __nv_bfloat16* sBh = sAl + AV_A_HALVES;
        const __nv_bfloat16* sBl = sBh + AV_B_HALVES;

        #pragma unroll
        for (int ks = 0; ks < 2; ks++) {   // two k16 steps per KC=32
            uint32_t ah[4][4], al[4][4], bh[4][2], bl[4][2];
            #pragma unroll
            for (int mf = 0; mf < 4; mf++) {
                const int m = m_w + mf * 16 + gr;
                const int base = m * AV_A_PAD + ks * 16 + 2 * gc;
                ah[mf][0] = *reinterpret_cast<const uint32_t*>(sAh + base);
                ah[mf][1] = *reinterpret_cast<const uint32_t*>(sAh + base + 8 * AV_A_PAD);
                ah[mf][2] = *reinterpret_cast<const uint32_t*>(sAh + base + 8);
                ah[mf][3] = *reinterpret_cast<const uint32_t*>(sAh + base + 8 * AV_A_PAD + 8);
                al[mf][0] = *reinterpret_cast<const uint32_t*>(sAl + base);
                al[mf][1] = *reinterpret_cast<const uint32_t*>(sAl + base + 8 * AV_A_PAD);
                al[mf][2] = *reinterpret_cast<const uint32_t*>(sAl + base + 8);
                al[mf][3] = *reinterpret_cast<const uint32_t*>(sAl + base + 8 * AV_A_PAD + 8);
            }
            #pragma unroll
            for (int nf = 0; nf < 4; nf++) {
                const int n = n_w + nf * 8 + gr;
                const int b0 = (ks * 8 + gc) * AV_B_PAD + n * 2;
                const int b1 = (ks * 8 + gc + 4) * AV_B_PAD + n * 2;
                bh[nf][0] = *reinterpret_cast<const uint32_t*>(sBh + b0);
                bh[nf][1] = *reinterpret_cast<const uint32_t*>(sBh + b1);
                bl[nf][0] = *reinterpret_cast<const uint32_t*>(sBl + b0);
                bl[nf][1] = *reinterpret_cast<const uint32_t*>(sBl + b1);
            }
            #pragma unroll
            for (int mf = 0; mf < 4; mf++)
                #pragma unroll
                for (int nf = 0; nf < 4; nf++)
                    mma16(acc[mf][nf], ah[mf], bh[nf]);
            #pragma unroll
            for (int mf = 0; mf < 4; mf++)
                #pragma unroll
                for (int nf = 0; nf < 4; nf++)
                    mma16(acc[mf][nf], al[mf], bh[nf]);
            #pragma unroll
            for (int mf = 0; mf < 4; mf++)
                #pragma unroll
                for (int nf = 0; nf < 4; nf++)
                    mma16(acc[mf][nf], ah[mf], bl[nf]);
        }
        if (c + 1 < NC) stsAB(s ^ 1);
        __syncthreads();
    }

    #pragma unroll
    for (int mf = 0; mf < 4; mf++)
        #pragma unroll
        for (int nf = 0; nf < 4; nf++) {
            const int mrow = m_w + mf * 16 + gr;
            const int ncol = n_w + nf * 8 + 2 * gc;
            float2 v0 = make_float2(acc[mf][nf][0], acc[mf][nf][1]);
            float2 v1 = make_float2(acc[mf][nf][2], acc[mf][nf][3]);
            *reinterpret_cast<float2*>(Cbase + (size_t)mrow * c_rs + ncol) = v0;
            *reinterpret_cast<float2*>(Cbase + (size_t)(mrow + 8) * c_rs + ncol) = v1;
        }
}

// ---------------------------------------------------------------------------
// LayerNorm in place on g_X rows (B*T rows of D)
// ---------------------------------------------------------------------------
__global__ __launch_bounds__(256) void k_ln(const float* __restrict__ gamma,
                                            const float* __restrict__ beta) {
    const int row = blockIdx.x;
    float* x = &g_X[(size_t)row * D];
    const int tid = threadIdx.x;

    float2 v = *reinterpret_cast<const float2*>(&x[tid * 2]);
    float s = v.x + v.y;
    float q = v.x * v.x + v.y * v.y;

    __shared__ float sh_s[8], sh_q[8];
    #pragma unroll
    for (int o = 16; o > 0; o >>= 1) {
        s += __shfl_xor_sync(0xffffffffu, s, o);
        q += __shfl_xor_sync(0xffffffffu, q, o);
    }
    if ((tid & 31) == 0) { sh_s[tid >> 5] = s; sh_q[tid >> 5] = q; }
    __syncthreads();
    float ts = 0.f, tq = 0.f;
    #pragma unroll
    for (int i = 0; i < 8; i++) { ts += sh_s[i]; tq += sh_q[i]; }

    const float mean = ts * (1.0f / D);
    const float var = tq * (1.0f / D) - mean * mean;
    const float rstd = rsqrtf(var + LN_EPS);

    float2 g = *reinterpret_cast<const float2*>(&gamma[tid * 2]);
    float2 bb = *reinterpret_cast<const float2*>(&beta[tid * 2]);
    float2 o;
    o.x = g.x * (v.x - mean) * rstd + bb.x;
    o.y = g.y * (v.y - mean) * rstd + bb.y;
    *reinterpret_cast<float2*>(&x[tid * 2]) = o;
}

// ---------------------------------------------------------------------------
// Softmax over S for each of B*T rows, in place
// ---------------------------------------------------------------------------
__global__ __launch_bounds__(256) void k_softmax(float* __restrict__ attn) {
    const size_t row = blockIdx.x;
    float* p = attn + row * (size_t)S;
    const int tid = threadIdx.x;

    float4 v0 = reinterpret_cast<const float4*>(p)[tid * 2 + 0];
    float4 v1 = reinterpret_cast<const float4*>(p)[tid * 2 + 1];

    float m = fmaxf(fmaxf(fmaxf(v0.x, v0.y), fmaxf(v0.z, v0.w)),
                    fmaxf(fmaxf(v1.x, v1.y), fmaxf(v1.z, v1.w)));
    __shared__ float sh[8];
    #pragma unroll
    for (int o = 16; o > 0; o >>= 1) m = fmaxf(m, __shfl_xor_sync(0xffffffffu, m, o));
    if ((tid & 31) == 0) sh[tid >> 5] = m;
    __syncthreads();
    float gm = sh[0];
    #pragma unroll
    for (int i = 1; i < 8; i++) gm = fmaxf(gm, sh[i]);
    __syncthreads();

    v0.x = __expf(v0.x - gm); v0.y = __expf(v0.y - gm);
    v0.z = __expf(v0.z - gm); v0.w = __expf(v0.w - gm);
    v1.x = __expf(v1.x - gm); v1.y = __expf(v1.y - gm);
    v1.z = __expf(v1.z - gm); v1.w = __expf(v1.w - gm);

    float s = v0.x + v0.y + v0.z + v0.w + v1.x + v1.y + v1.z + v1.w;
    #pragma unroll
    for (int o = 16; o > 0; o >>= 1) s += __shfl_xor_sync(0xffffffffu, s, o);
    if ((tid & 31) == 0) sh[tid >> 5] = s;
    __syncthreads();
    float gs = 0.f;
    #pragma unroll
    for (int i = 0; i < 8; i++) gs += sh[i];
    const float inv = 1.0f / gs;

    v0.x *= inv; v0.y *= inv; v0.z *= inv; v0.w *= inv;
    v1.x *= inv; v1.y *= inv; v1.z *= inv; v1.w *= inv;
    reinterpret_cast<float4*>(p)[tid * 2 + 0] = v0;
    reinterpret_cast<float4*>(p)[tid * 2 + 1] = v1;
}

// ---------------------------------------------------------------------------
extern "C" void kernel_launch(void* const* d_in, const int* in_sizes, int n_in,
                              void* d_out, int out_size) {
    const float* inp    = (const float*)d_in[0];  // [T,B,D]
    const float* ctx    = (const float*)d_in[1];  // [B,S,D]
    const float* values = (const float*)d_in[2];  // [B,S,D]
    const float* W      = (const float*)d_in[3];  // [D,D]
    const float* gamma  = (const float*)d_in[4];  // [D]
    const float* beta   = (const float*)d_in[5];  // [D]

    float* out_wc   = (float*)d_out;                       // [T,B,D]
    float* out_attn = (float*)d_out + (size_t)T * B * D;   // [B*T,S]

    cudaFuncSetAttribute(k_gemm<0>, cudaFuncAttributeMaxDynamicSharedMemorySize, GEMM_SMEM);
    cudaFuncSetAttribute(k_gemm<1>, cudaFuncAttributeMaxDynamicSharedMemorySize, GEMM_SMEM);
    cudaFuncSetAttribute(k_gemm_av, cudaFuncAttributeMaxDynamicSharedMemorySize, AV_SMEM);

    // 1) linear: g_X = inp @ W^T (rows b*T+t)
    {
        dim3 grid(D / 128, (B * T) / 128, 1);
        k_gemm<0><<<grid, 256, GEMM_SMEM>>>(inp, W, nullptr);
    }
    // 2) LayerNorm in place
    k_ln<<<B * T, 256>>>(gamma, beta);
    // 3) scores -> attn region
    {
        dim3 grid(S / 128, T / 128, B);
        k_gemm<1><<<grid, 256, GEMM_SMEM>>>(nullptr, ctx, out_attn);
    }
    // 4) softmax in place
    k_softmax<<<B * T, 256>>>(out_attn);
    // 5) weightedContext (bf16x3 split MMA)
    {
        dim3 grid(D / 128, T / 128, B);
        k_gemm_av<<<grid, 256, AV_SMEM>>>(out_attn, values, out_wc);
    }
}

// round 9
// speedup vs baseline: 2.3445x; 1.2262x over previous
#include <cuda_runtime.h>
#include <cuda_bf16.h>
#include <cstdint>

// Problem dims (fixed)
static constexpr int T = 1024, B = 32, S = 2048, D = 512;
static constexpr float LN_EPS = 1e-6f;

// Scratch: linear+LN output [B][T][D]
__device__ __align__(256) float g_X[(size_t)B * T * D];

// ---------------------------------------------------------------------------
__device__ __forceinline__ float f2tf(float x) {
    uint32_t r; asm("cvt.rna.tf32.f32 %0, %1;" : "=r"(r) : "f"(x));
    return __uint_as_float(r);
}
__device__ __forceinline__ void mma8(float* d, const uint32_t* a, const uint32_t* b) {
    asm volatile(
        "mma.sync.aligned.m16n8k8.row.col.f32.tf32.tf32.f32 "
        "{%0,%1,%2,%3}, {%4,%5,%6,%7}, {%8,%9}, {%0,%1,%2,%3};"
        : "+f"(d[0]), "+f"(d[1]), "+f"(d[2]), "+f"(d[3])
        : "r"(a[0]), "r"(a[1]), "r"(a[2]), "r"(a[3]), "r"(b[0]), "r"(b[1]));
}
__device__ __forceinline__ void mma16(float* d, const uint32_t* a, const uint32_t* b) {
    asm volatile(
        "mma.sync.aligned.m16n8k16.row.col.f32.bf16.bf16.f32 "
        "{%0,%1,%2,%3}, {%4,%5,%6,%7}, {%8,%9}, {%0,%1,%2,%3};"
        : "+f"(d[0]), "+f"(d[1]), "+f"(d[2]), "+f"(d[3])
        : "r"(a[0]), "r"(a[1]), "r"(a[2]), "r"(a[3]), "r"(b[0]), "r"(b[1]));
}

// ---------------------------------------------------------------------------
// Split-TF32 GEMM (linear only): C[M,N] = inp(row b*T+t)[M,K] * W[N,K]^T, K=512
// CTA tile 128x128, KC=32, double-buffered, 256 threads, warp tile 64x32.
// Kept in tf32x3: linear errors get sqrt(D)-amplified through the scores
// dot product, so this GEMM needs the extra precision.
// ---------------------------------------------------------------------------
static constexpr int KC = 32;
static constexpr int LDS_P = 36;
static constexpr int REG_FLOATS = 128 * LDS_P;          // 4608
static constexpr int STAGE_FLOATS = 4 * REG_FLOATS;
static constexpr int GEMM_SMEM = 2 * STAGE_FLOATS * 4;  // 147456 bytes

__global__ __launch_bounds__(256) void k_gemm_lin(const float* __restrict__ Ap,
                                                  const float* __restrict__ Bp) {
    extern __shared__ float sm[];
    constexpr int NC = D / KC;

    const int tid = threadIdx.x;
    const int n0 = blockIdx.x * 128;
    const int m0 = blockIdx.y * 128;

    const int bb = m0 >> 10, t0 = m0 & 1023;
    const float* Abase = Ap + ((size_t)t0 * B + bb) * D;
    const size_t a_rs = (size_t)B * D;
    const float* Bbase = Bp + (size_t)n0 * D;
    float* Cbase = g_X + (size_t)m0 * D + n0;

    const int lane = tid & 31, wid = tid >> 5;
    const int gr = lane >> 2, gc = lane & 3;
    const int m_w = (wid >> 2) * 64;
    const int n_w = (wid & 3) * 32;

    const int prow = tid >> 3;
    const int pkq = (tid & 7) * 4;

    float4 na[4], nb[4];

    auto loadAB = [&](int c) {
        const int k0 = c * KC;
        #pragma unroll
        for (int j = 0; j < 4; j++) {
            const int row = prow + 32 * j;
            na[j] = *reinterpret_cast<const float4*>(Abase + (size_t)row * a_rs + k0 + pkq);
            nb[j] = *reinterpret_cast<const float4*>(Bbase + (size_t)row * D + k0 + pkq);
        }
    };
    auto stsAB = [&](int s) {
        float* sAh = sm + s * STAGE_FLOATS;
        float* sAl = sAh + REG_FLOATS;
        float* sBh = sAl + REG_FLOATS;
        float* sBl = sBh + REG_FLOATS;
        #pragma unroll
        for (int j = 0; j < 4; j++) {
            const int off = (prow + 32 * j) * LDS_P + pkq;
            float4 v = na[j];
            float4 h, l;
            h.x = f2tf(v.x); l.x = f2tf(v.x - h.x);
            h.y = f2tf(v.y); l.y = f2tf(v.y - h.y);
            h.z = f2tf(v.z); l.z = f2tf(v.z - h.z);
            h.w = f2tf(v.w); l.w = f2tf(v.w - h.w);
            *reinterpret_cast<float4*>(sAh + off) = h;
            *reinterpret_cast<float4*>(sAl + off) = l;
            v = nb[j];
            h.x = f2tf(v.x); l.x = f2tf(v.x - h.x);
            h.y = f2tf(v.y); l.y = f2tf(v.y - h.y);
            h.z = f2tf(v.z); l.z = f2tf(v.z - h.z);
            h.w = f2tf(v.w); l.w = f2tf(v.w - h.w);
            *reinterpret_cast<float4*>(sBh + off) = h;
            *reinterpret_cast<float4*>(sBl + off) = l;
        }
    };

    float acc[4][4][4];
    #pragma unroll
    for (int i = 0; i < 4; i++)
        #pragma unroll
        for (int j = 0; j < 4; j++)
            #pragma unroll
            for (int q = 0; q < 4; q++) acc[i][j][q] = 0.f;

    loadAB(0);
    stsAB(0);
    __syncthreads();

    for (int c = 0; c < NC; c++) {
        const int s = c & 1;
        if (c + 1 < NC) loadAB(c + 1);

        const float* sAh = sm + s * STAGE_FLOATS;
        const float* sAl = sAh + REG_FLOATS;
        const float* sBh = sAl + REG_FLOATS;
        const float* sBl = sBh + REG_FLOATS;

        #pragma unroll
        for (int ks = 0; ks < 4; ks++) {
            uint32_t ah[4][4], al[4][4], bh[4][2], bl[4][2];
            #pragma unroll
            for (int mf = 0; mf < 4; mf++) {
                const int base = (m_w + mf * 16 + gr) * LDS_P + ks * 8 + gc;
                ah[mf][0] = __float_as_uint(sAh[base]);
                ah[mf][1] = __float_as_uint(sAh[base + 8 * LDS_P]);
                ah[mf][2] = __float_as_uint(sAh[base + 4]);
                ah[mf][3] = __float_as_uint(sAh[base + 8 * LDS_P + 4]);
                al[mf][0] = __float_as_uint(sAl[base]);
                al[mf][1] = __float_as_uint(sAl[base + 8 * LDS_P]);
                al[mf][2] = __float_as_uint(sAl[base + 4]);
                al[mf][3] = __float_as_uint(sAl[base + 8 * LDS_P + 4]);
            }
            #pragma unroll
            for (int nf = 0; nf < 4; nf++) {
                const int base = (n_w + nf * 8 + gr) * LDS_P + ks * 8 + gc;
                bh[nf][0] = __float_as_uint(sBh[base]);
                bh[nf][1] = __float_as_uint(sBh[base + 4]);
                bl[nf][0] = __float_as_uint(sBl[base]);
                bl[nf][1] = __float_as_uint(sBl[base + 4]);
            }
            #pragma unroll
            for (int mf = 0; mf < 4; mf++)
                #pragma unroll
                for (int nf = 0; nf < 4; nf++)
                    mma8(acc[mf][nf], ah[mf], bh[nf]);
            #pragma unroll
            for (int mf = 0; mf < 4; mf++)
                #pragma unroll
                for (int nf = 0; nf < 4; nf++)
                    mma8(acc[mf][nf], al[mf], bh[nf]);
            #pragma unroll
            for (int mf = 0; mf < 4; mf++)
                #pragma unroll
                for (int nf = 0; nf < 4; nf++)
                    mma8(acc[mf][nf], ah[mf], bl[nf]);
        }
        if (c + 1 < NC) stsAB(s ^ 1);
        __syncthreads();
    }

    #pragma unroll
    for (int mf = 0; mf < 4; mf++)
        #pragma unroll
        for (int nf = 0; nf < 4; nf++) {
            const int mrow = m_w + mf * 16 + gr;
            const int ncol = n_w + nf * 8 + 2 * gc;
            float2 v0 = make_float2(acc[mf][nf][0], acc[mf][nf][1]);
            float2 v1 = make_float2(acc[mf][nf][2], acc[mf][nf][3]);
            *reinterpret_cast<float2*>(Cbase + (size_t)mrow * D + ncol) = v0;
            *reinterpret_cast<float2*>(Cbase + (size_t)(mrow + 8) * D + ncol) = v1;
        }
}

// ---------------------------------------------------------------------------
// Scores GEMM in split-BF16 (bf16x3), NT: attnlogits = g_X[M,K] * ctx[N,K]^T
// CTA tile 128x128, KC=32, double-buffered, 256 threads, warp tile 64x32.
// A,B smem: bf16 [row][k], pad 40 halves per row.
// ---------------------------------------------------------------------------
static constexpr int SC_PAD = 40;                        // halves per row
static constexpr int SC_REG = 128 * SC_PAD;              // 5120 halves / region
static constexpr int SC_STAGE = 4 * SC_REG;              // 20480 halves
static constexpr int SC_SMEM = 2 * SC_STAGE * 2;         // 81920 bytes

__global__ __launch_bounds__(256) void k_gemm_sc(const float* __restrict__ ctx,
                                                 float* __restrict__ attn) {
    extern __shared__ __nv_bfloat16 smh[];
    constexpr int NC = D / KC;   // 16

    const int tid = threadIdx.x;
    const int n0 = blockIdx.x * 128;
    const int m0 = blockIdx.y * 128;
    const int bz = blockIdx.z;

    const float* Abase = g_X + ((size_t)bz * T + m0) * D;
    const float* Bbase = ctx + ((size_t)bz * S + n0) * D;
    float* Cbase = attn + ((size_t)bz * T + m0) * S + n0;

    const int lane = tid & 31, wid = tid >> 5;
    const int gr = lane >> 2, gc = lane & 3;
    const int m_w = (wid >> 2) * 64;
    const int n_w = (wid & 3) * 32;

    const int prow = tid >> 3;
    const int pkq = (tid & 7) * 4;

    float4 na[4], nb[4];

    auto loadAB = [&](int c) {
        const int k0 = c * KC;
        #pragma unroll
        for (int j = 0; j < 4; j++) {
            const int row = prow + 32 * j;
            na[j] = *reinterpret_cast<const float4*>(Abase + (size_t)row * D + k0 + pkq);
            nb[j] = *reinterpret_cast<const float4*>(Bbase + (size_t)row * D + k0 + pkq);
        }
    };
    auto cvt_store = [&](__nv_bfloat16* hi, __nv_bfloat16* lo, int off, float4 v) {
        __nv_bfloat16 h0 = __float2bfloat16(v.x);
        __nv_bfloat16 h1 = __float2bfloat16(v.y);
        __nv_bfloat16 h2 = __float2bfloat16(v.z);
        __nv_bfloat16 h3 = __float2bfloat16(v.w);
        __nv_bfloat162 hp0 = {h0, h1}, hp1 = {h2, h3};
        __nv_bfloat162 lp0 = {__float2bfloat16(v.x - __bfloat162float(h0)),
                              __float2bfloat16(v.y - __bfloat162float(h1))};
        __nv_bfloat162 lp1 = {__float2bfloat16(v.z - __bfloat162float(h2)),
                              __float2bfloat16(v.w - __bfloat162float(h3))};
        *reinterpret_cast<__nv_bfloat162*>(hi + off) = hp0;
        *reinterpret_cast<__nv_bfloat162*>(hi + off + 2) = hp1;
        *reinterpret_cast<__nv_bfloat162*>(lo + off) = lp0;
        *reinterpret_cast<__nv_bfloat162*>(lo + off + 2) = lp1;
    };
    auto stsAB = [&](int s) {
        __nv_bfloat16* sAh = smh + s * SC_STAGE;
        __nv_bfloat16* sAl = sAh + SC_REG;
        __nv_bfloat16* sBh = sAl + SC_REG;
        __nv_bfloat16* sBl = sBh + SC_REG;
        #pragma unroll
        for (int j = 0; j < 4; j++) {
            const int off = (prow + 32 * j) * SC_PAD + pkq;
            cvt_store(sAh, sAl, off, na[j]);
            cvt_store(sBh, sBl, off, nb[j]);
        }
    };

    float acc[4][4][4];
    #pragma unroll
    for (int i = 0; i < 4; i++)
        #pragma unroll
        for (int j = 0; j < 4; j++)
            #pragma unroll
            for (int q = 0; q < 4; q++) acc[i][j][q] = 0.f;

    loadAB(0);
    stsAB(0);
    __syncthreads();

    for (int c = 0; c < NC; c++) {
        const int s = c & 1;
        if (c + 1 < NC) loadAB(c + 1);

        const __nv_bfloat16* sAh = smh + s * SC_STAGE;
        const __nv_bfloat16* sAl = sAh + SC_REG;
        const __nv_bfloat16* sBh = sAl + SC_REG;
        const __nv_bfloat16* sBl = sBh + SC_REG;

        #pragma unroll
        for (int ks = 0; ks < 2; ks++) {   // two k16 steps per KC=32
            uint32_t ah[4][4], al[4][4], bh[4][2], bl[4][2];
            #pragma unroll
            for (int mf = 0; mf < 4; mf++) {
                const int base = (m_w + mf * 16 + gr) * SC_PAD + ks * 16 + 2 * gc;
                ah[mf][0] = *reinterpret_cast<const uint32_t*>(sAh + base);
                ah[mf][1] = *reinterpret_cast<const uint32_t*>(sAh + base + 8 * SC_PAD);
                ah[mf][2] = *reinterpret_cast<const uint32_t*>(sAh + base + 8);
                ah[mf][3] = *reinterpret_cast<const uint32_t*>(sAh + base + 8 * SC_PAD + 8);
                al[mf][0] = *reinterpret_cast<const uint32_t*>(sAl + base);
                al[mf][1] = *reinterpret_cast<const uint32_t*>(sAl + base + 8 * SC_PAD);
                al[mf][2] = *reinterpret_cast<const uint32_t*>(sAl + base + 8);
                al[mf][3] = *reinterpret_cast<const uint32_t*>(sAl + base + 8 * SC_PAD + 8);
            }
            #pragma unroll
            for (int nf = 0; nf < 4; nf++) {
                const int base = (n_w + nf * 8 + gr) * SC_PAD + ks * 16 + 2 * gc;
                bh[nf][0] = *reinterpret_cast<const uint32_t*>(sBh + base);
                bh[nf][1] = *reinterpret_cast<const uint32_t*>(sBh + base + 8);
                bl[nf][0] = *reinterpret_cast<const uint32_t*>(sBl + base);
                bl[nf][1] = *reinterpret_cast<const uint32_t*>(sBl + base + 8);
            }
            #pragma unroll
            for (int mf = 0; mf < 4; mf++)
                #pragma unroll
                for (int nf = 0; nf < 4; nf++)
                    mma16(acc[mf][nf], ah[mf], bh[nf]);
            #pragma unroll
            for (int mf = 0; mf < 4; mf++)
                #pragma unroll
                for (int nf = 0; nf < 4; nf++)
                    mma16(acc[mf][nf], al[mf], bh[nf]);
            #pragma unroll
            for (int mf = 0; mf < 4; mf++)
                #pragma unroll
                for (int nf = 0; nf < 4; nf++)
                    mma16(acc[mf][nf], ah[mf], bl[nf]);
        }
        if (c + 1 < NC) stsAB(s ^ 1);
        __syncthreads();
    }

    #pragma unroll
    for (int mf = 0; mf < 4; mf++)
        #pragma unroll
        for (int nf = 0; nf < 4; nf++) {
            const int mrow = m_w + mf * 16 + gr;
            const int ncol = n_w + nf * 8 + 2 * gc;
            float2 v0 = make_float2(acc[mf][nf][0], acc[mf][nf][1]);
            float2 v1 = make_float2(acc[mf][nf][2], acc[mf][nf][3]);
            *reinterpret_cast<float2*>(Cbase + (size_t)mrow * S + ncol) = v0;
            *reinterpret_cast<float2*>(Cbase + (size_t)(mrow + 8) * S + ncol) = v1;
        }
}

// ---------------------------------------------------------------------------
// AV GEMM in split-BF16: out[t][b][d] = sum_s attn[b][t][s]*values[b][s][d]
// (unchanged from R8)
// ---------------------------------------------------------------------------
static constexpr int AV_A_PAD = 40;
static constexpr int AV_A_HALVES = 128 * AV_A_PAD;        // 5120
static constexpr int AV_B_PAD = 272;
static constexpr int AV_B_HALVES = 16 * AV_B_PAD;         // 4352
static constexpr int AV_STAGE_HALVES = 2 * AV_A_HALVES + 2 * AV_B_HALVES;  // 18944
static constexpr int AV_SMEM = 2 * AV_STAGE_HALVES * 2;   // 75776 bytes

__global__ __launch_bounds__(256) void k_gemm_av(const float* __restrict__ attn,
                                                 const float* __restrict__ values,
                                                 float* __restrict__ out) {
    extern __shared__ __nv_bfloat16 smh[];
    constexpr int NC = S / KC;   // 64

    const int tid = threadIdx.x;
    const int n0 = blockIdx.x * 128;
    const int m0 = blockIdx.y * 128;
    const int bz = blockIdx.z;

    const float* Abase = attn + ((size_t)bz * T + m0) * S;
    const float* Bbase = values + (size_t)bz * S * D + n0;
    float* Cbase = out + (size_t)m0 * B * D + (size_t)bz * D + n0;
    const size_t c_rs = (size_t)B * D;

    const int lane = tid & 31, wid = tid >> 5;
    const int gr = lane >> 2, gc = lane & 3;
    const int m_w = (wid >> 2) * 64;
    const int n_w = (wid & 3) * 32;

    const int prow = tid >> 3;
    const int pkq = (tid & 7) * 4;
    const int qrow = tid >> 5;
    const int qcol = (tid & 31) * 4;

    float4 na[4], nb[4];

    auto loadAB = [&](int c) {
        const int k0 = c * KC;
        #pragma unroll
        for (int j = 0; j < 4; j++) {
            na[j] = *reinterpret_cast<const float4*>(Abase + (size_t)(prow + 32 * j) * S + k0 + pkq);
            nb[j] = *reinterpret_cast<const float4*>(Bbase + (size_t)(k0 + qrow + 8 * j) * D + qcol);
        }
    };
    auto stsAB = [&](int s) {
        __nv_bfloat16* sAh = smh + s * AV_STAGE_HALVES;
        __nv_bfloat16* sAl = sAh + AV_A_HALVES;
        __nv_bfloat16* sBh = sAl + AV_A_HALVES;
        __nv_bfloat16* sBl = sBh + AV_B_HALVES;
        #pragma unroll
        for (int j = 0; j < 4; j++) {
            const int off = (prow + 32 * j) * AV_A_PAD + pkq;
            const float4 v = na[j];
            __nv_bfloat16 h0 = __float2bfloat16(v.x);
            __nv_bfloat16 h1 = __float2bfloat16(v.y);
            __nv_bfloat16 h2 = __float2bfloat16(v.z);
            __nv_bfloat16 h3 = __float2bfloat16(v.w);
            __nv_bfloat162 hp0 = {h0, h1}, hp1 = {h2, h3};
            __nv_bfloat162 lp0 = {__float2bfloat16(v.x - __bfloat162float(h0)),
                                  __float2bfloat16(v.y - __bfloat162float(h1))};
            __nv_bfloat162 lp1 = {__float2bfloat16(v.z - __bfloat162float(h2)),
                                  __float2bfloat16(v.w - __bfloat162float(h3))};
            *reinterpret_cast<__nv_bfloat162*>(sAh + off) = hp0;
            *reinterpret_cast<__nv_bfloat162*>(sAh + off + 2) = hp1;
            *reinterpret_cast<__nv_bfloat162*>(sAl + off) = lp0;
            *reinterpret_cast<__nv_bfloat162*>(sAl + off + 2) = lp1;
        }
        #pragma unroll
        for (int j = 0; j < 4; j++) {
            const int kk = qrow + 8 * j;
            const int kp = kk >> 1, slot = kk & 1;
            const int base = kp * AV_B_PAD + qcol * 2 + slot;
            const float4 v = nb[j];
            const float vv[4] = {v.x, v.y, v.z, v.w};
            #pragma unroll
            for (int i = 0; i < 4; i++) {
                __nv_bfloat16 h = __float2bfloat16(vv[i]);
                sBh[base + i * 2] = h;
                sBl[base + i * 2] = __float2bfloat16(vv[i] - __bfloat162float(h));
            }
        }
    };

    float acc[4][4][4];
    #pragma unroll
    for (int i = 0; i < 4; i++)
        #pragma unroll
        for (int j = 0; j < 4; j++)
            #pragma unroll
            for (int q = 0; q < 4; q++) acc[i][j][q] = 0.f;

    loadAB(0);
    stsAB(0);
    __syncthreads();

    for (int c = 0; c < NC; c++) {
        const int s = c & 1;
        if (c + 1 < NC) loadAB(c + 1);

        const __nv_bfloat16* sAh = smh + s * AV_STAGE_HALVES;
        const __nv_bfloat16* sAl = sAh + AV_A_HALVES;
        const __nv_bfloat16* sBh = sAl + AV_A_HALVES;
        const __nv_bfloat16* sBl = sBh + AV_B_HALVES;

        #pragma unroll
        for (int ks = 0; ks < 2; ks++) {
            uint32_t ah[4][4], al[4][4], bh[4][2], bl[4][2];
            #pragma unroll
            for (int mf = 0; mf < 4; mf++) {
                const int m = m_w + mf * 16 + gr;
                const int base = m * AV_A_PAD + ks * 16 + 2 * gc;
                ah[mf][0] = *reinterpret_cast<const uint32_t*>(sAh + base);
                ah[mf][1] = *reinterpret_cast<const uint32_t*>(sAh + base + 8 * AV_A_PAD);
                ah[mf][2] = *reinterpret_cast<const uint32_t*>(sAh + base + 8);
                ah[mf][3] = *reinterpret_cast<const uint32_t*>(sAh + base + 8 * AV_A_PAD + 8);
                al[mf][0] = *reinterpret_cast<const uint32_t*>(sAl + base);
                al[mf][1] = *reinterpret_cast<const uint32_t*>(sAl + base + 8 * AV_A_PAD);
                al[mf][2] = *reinterpret_cast<const uint32_t*>(sAl + base + 8);
                al[mf][3] = *reinterpret_cast<const uint32_t*>(sAl + base + 8 * AV_A_PAD + 8);
            }
            #pragma unroll
            for (int nf = 0; nf < 4; nf++) {
                const int n = n_w + nf * 8 + gr;
                const int b0 = (ks * 8 + gc) * AV_B_PAD + n * 2;
                const int b1 = (ks * 8 + gc + 4) * AV_B_PAD + n * 2;
                bh[nf][0] = *reinterpret_cast<const uint32_t*>(sBh + b0);
                bh[nf][1] = *reinterpret_cast<const uint32_t*>(sBh + b1);
                bl[nf][0] = *reinterpret_cast<const uint32_t*>(sBl + b0);
                bl[nf][1] = *reinterpret_cast<const uint32_t*>(sBl + b1);
            }
            #pragma unroll
            for (int mf = 0; mf < 4; mf++)
                #pragma unroll
                for (int nf = 0; nf < 4; nf++)
                    mma16(acc[mf][nf], ah[mf], bh[nf]);
            #pragma unroll
            for (int mf = 0; mf < 4; mf++)
                #pragma unroll
                for (int nf = 0; nf < 4; nf++)
                    mma16(acc[mf][nf], al[mf], bh[nf]);
            #pragma unroll
            for (int mf = 0; mf < 4; mf++)
                #pragma unroll
                for (int nf = 0; nf < 4; nf++)
                    mma16(acc[mf][nf], ah[mf], bl[nf]);
        }
        if (c + 1 < NC) stsAB(s ^ 1);
        __syncthreads();
    }

    #pragma unroll
    for (int mf = 0; mf < 4; mf++)
        #pragma unroll
        for (int nf = 0; nf < 4; nf++) {
            const int mrow = m_w + mf * 16 + gr;
            const int ncol = n_w + nf * 8 + 2 * gc;
            float2 v0 = make_float2(acc[mf][nf][0], acc[mf][nf][1]);
            float2 v1 = make_float2(acc[mf][nf][2], acc[mf][nf][3]);
            *reinterpret_cast<float2*>(Cbase + (size_t)mrow * c_rs + ncol) = v0;
            *reinterpret_cast<float2*>(Cbase + (size_t)(mrow + 8) * c_rs + ncol) = v1;
        }
}

// ---------------------------------------------------------------------------
// LayerNorm in place on g_X rows (B*T rows of D)
// ---------------------------------------------------------------------------
__global__ __launch_bounds__(256) void k_ln(const float* __restrict__ gamma,
                                            const float* __restrict__ beta) {
    const int row = blockIdx.x;
    float* x = &g_X[(size_t)row * D];
    const int tid = threadIdx.x;

    float2 v = *reinterpret_cast<const float2*>(&x[tid * 2]);
    float s = v.x + v.y;
    float q = v.x * v.x + v.y * v.y;

    __shared__ float sh_s[8], sh_q[8];
    #pragma unroll
    for (int o = 16; o > 0; o >>= 1) {
        s += __shfl_xor_sync(0xffffffffu, s, o);
        q += __shfl_xor_sync(0xffffffffu, q, o);
    }
    if ((tid & 31) == 0) { sh_s[tid >> 5] = s; sh_q[tid >> 5] = q; }
    __syncthreads();
    float ts = 0.f, tq = 0.f;
    #pragma unroll
    for (int i = 0; i < 8; i++) { ts += sh_s[i]; tq += sh_q[i]; }

    const float mean = ts * (1.0f / D);
    const float var = tq * (1.0f / D) - mean * mean;
    const float rstd = rsqrtf(var + LN_EPS);

    float2 g = *reinterpret_cast<const float2*>(&gamma[tid * 2]);
    float2 bb = *reinterpret_cast<const float2*>(&beta[tid * 2]);
    float2 o;
    o.x = g.x * (v.x - mean) * rstd + bb.x;
    o.y = g.y * (v.y - mean) * rstd + bb.y;
    *reinterpret_cast<float2*>(&x[tid * 2]) = o;
}

// ---------------------------------------------------------------------------
// Softmax over S for each of B*T rows, in place
// ---------------------------------------------------------------------------
__global__ __launch_bounds__(256) void k_softmax(float* __restrict__ attn) {
    const size_t row = blockIdx.x;
    float* p = attn + row * (size_t)S;
    const int tid = threadIdx.x;

    float4 v0 = reinterpret_cast<const float4*>(p)[tid * 2 + 0];
    float4 v1 = reinterpret_cast<const float4*>(p)[tid * 2 + 1];

    float m = fmaxf(fmaxf(fmaxf(v0.x, v0.y), fmaxf(v0.z, v0.w)),
                    fmaxf(fmaxf(v1.x, v1.y), fmaxf(v1.z, v1.w)));
    __shared__ float sh[8];
    #pragma unroll
    for (int o = 16; o > 0; o >>= 1) m = fmaxf(m, __shfl_xor_sync(0xffffffffu, m, o));
    if ((tid & 31) == 0) sh[tid >> 5] = m;
    __syncthreads();
    float gm = sh[0];
    #pragma unroll
    for (int i = 1; i < 8; i++) gm = fmaxf(gm, sh[i]);
    __syncthreads();

    v0.x = __expf(v0.x - gm); v0.y = __expf(v0.y - gm);
    v0.z = __expf(v0.z - gm); v0.w = __expf(v0.w - gm);
    v1.x = __expf(v1.x - gm); v1.y = __expf(v1.y - gm);
    v1.z = __expf(v1.z - gm); v1.w = __expf(v1.w - gm);

    float s = v0.x + v0.y + v0.z + v0.w + v1.x + v1.y + v1.z + v1.w;
    #pragma unroll
    for (int o = 16; o > 0; o >>= 1) s += __shfl_xor_sync(0xffffffffu, s, o);
    if ((tid & 31) == 0) sh[tid >> 5] = s;
    __syncthreads();
    float gs = 0.f;
    #pragma unroll
    for (int i = 0; i < 8; i++) gs += sh[i];
    const float inv = 1.0f / gs;

    v0.x *= inv; v0.y *= inv; v0.z *= inv; v0.w *= inv;
    v1.x *= inv; v1.y *= inv; v1.z *= inv; v1.w *= inv;
    reinterpret_cast<float4*>(p)[tid * 2 + 0] = v0;
    reinterpret_cast<float4*>(p)[tid * 2 + 1] = v1;
}

// ---------------------------------------------------------------------------
extern "C" void kernel_launch(void* const* d_in, const int* in_sizes, int n_in,
                              void* d_out, int out_size) {
    const float* inp    = (const float*)d_in[0];  // [T,B,D]
    const float* ctx    = (const float*)d_in[1];  // [B,S,D]
    const float* values = (const float*)d_in[2];  // [B,S,D]
    const float* W      = (const float*)d_in[3];  // [D,D]
    const float* gamma  = (const float*)d_in[4];  // [D]
    const float* beta   = (const float*)d_in[5];  // [D]

    float* out_wc   = (float*)d_out;                       // [T,B,D]
    float* out_attn = (float*)d_out + (size_t)T * B * D;   // [B*T,S]

    cudaFuncSetAttribute(k_gemm_lin, cudaFuncAttributeMaxDynamicSharedMemorySize, GEMM_SMEM);
    cudaFuncSetAttribute(k_gemm_sc, cudaFuncAttributeMaxDynamicSharedMemorySize, SC_SMEM);
    cudaFuncSetAttribute(k_gemm_av, cudaFuncAttributeMaxDynamicSharedMemorySize, AV_SMEM);

    // 1) linear: g_X = inp @ W^T (rows b*T+t)  [tf32x3 for precision]
    {
        dim3 grid(D / 128, (B * T) / 128, 1);
        k_gemm_lin<<<grid, 256, GEMM_SMEM>>>(inp, W);
    }
    // 2) LayerNorm in place
    k_ln<<<B * T, 256>>>(gamma, beta);
    // 3) scores -> attn region  [bf16x3]
    {
        dim3 grid(S / 128, T / 128, B);
        k_gemm_sc<<<grid, 256, SC_SMEM>>>(ctx, out_attn);
    }
    // 4) softmax in place
    k_softmax<<<B * T, 256>>>(out_attn);
    // 5) weightedContext  [bf16x3]
    {
        dim3 grid(D / 128, T / 128, B);
        k_gemm_av<<<grid, 256, AV_SMEM>>>(out_attn, values, out_wc);
    }
}

// round 10
// speedup vs baseline: 2.7417x; 1.1694x over previous
#include <cuda_runtime.h>
#include <cuda_bf16.h>
#include <cstdint>

// Problem dims (fixed)
static constexpr int T = 1024, B = 32, S = 2048, D = 512;
static constexpr float LN_EPS = 1e-6f;

// Scratch: linear+LN output [B][T][D]
__device__ __align__(256) float g_X[(size_t)B * T * D];

// ---------------------------------------------------------------------------
__device__ __forceinline__ void mma16(float* d, const uint32_t* a, const uint32_t* b) {
    asm volatile(
        "mma.sync.aligned.m16n8k16.row.col.f32.bf16.bf16.f32 "
        "{%0,%1,%2,%3}, {%4,%5,%6,%7}, {%8,%9}, {%0,%1,%2,%3};"
        : "+f"(d[0]), "+f"(d[1]), "+f"(d[2]), "+f"(d[3])
        : "r"(a[0]), "r"(a[1]), "r"(a[2]), "r"(a[3]), "r"(b[0]), "r"(b[1]));
}
__device__ __forceinline__ uint32_t packbf(float x, float y) {
    __nv_bfloat162 t = __floats2bfloat162_rn(x, y);
    return *reinterpret_cast<uint32_t*>(&t);
}

static constexpr int KC = 32;

// ---------------------------------------------------------------------------
// NT split-BF16 GEMM (bf16x3): C[M,N] = A[M,K]*B[N,K]^T, K=512, KC=32.
// MODE 0: linear  A=inp(row b*T+t), B=W,   C=g_X
// MODE 1: scores  A=g_X,            B=ctx, C=attn
// CTA tile 128x128, 256 threads, warp tile 64x32, double-buffered.
// A,B smem: bf16 [row][k], pad 40 halves per row.
// ---------------------------------------------------------------------------
static constexpr int SC_PAD = 40;                        // halves per row
static constexpr int SC_REG = 128 * SC_PAD;              // 5120 halves / region
static constexpr int SC_STAGE = 4 * SC_REG;              // 20480 halves
static constexpr int SC_SMEM = 2 * SC_STAGE * 2;         // 81920 bytes

template <int MODE>
__global__ __launch_bounds__(256) void k_gemm_nt(const float* __restrict__ Ap,
                                                 const float* __restrict__ Bp,
                                                 float* __restrict__ Cp) {
    extern __shared__ __nv_bfloat16 smh[];
    constexpr int NC = D / KC;   // 16

    const int tid = threadIdx.x;
    const int n0 = blockIdx.x * 128;
    const int m0 = blockIdx.y * 128;
    const int bz = blockIdx.z;

    const float* Abase; size_t a_rs;
    const float* Bbase;
    float* Cbase; size_t c_rs;
    if (MODE == 0) {
        const int bb = m0 >> 10, t0 = m0 & 1023;
        Abase = Ap + ((size_t)t0 * B + bb) * D; a_rs = (size_t)B * D;
        Bbase = Bp + (size_t)n0 * D;
        Cbase = g_X + (size_t)m0 * D + n0;      c_rs = D;
    } else {
        Abase = g_X + ((size_t)bz * T + m0) * D;     a_rs = D;
        Bbase = Bp + ((size_t)bz * S + n0) * D;
        Cbase = Cp + ((size_t)bz * T + m0) * S + n0; c_rs = S;
    }

    const int lane = tid & 31, wid = tid >> 5;
    const int gr = lane >> 2, gc = lane & 3;
    const int m_w = (wid >> 2) * 64;
    const int n_w = (wid & 3) * 32;

    const int prow = tid >> 3;
    const int pkq = (tid & 7) * 4;

    float4 na[4], nb[4];

    auto loadAB = [&](int c) {
        const int k0 = c * KC;
        #pragma unroll
        for (int j = 0; j < 4; j++) {
            const int row = prow + 32 * j;
            na[j] = *reinterpret_cast<const float4*>(Abase + (size_t)row * a_rs + k0 + pkq);
            nb[j] = *reinterpret_cast<const float4*>(Bbase + (size_t)row * D + k0 + pkq);
        }
    };
    auto cvt_store = [&](__nv_bfloat16* hi, __nv_bfloat16* lo, int off, float4 v) {
        __nv_bfloat16 h0 = __float2bfloat16(v.x);
        __nv_bfloat16 h1 = __float2bfloat16(v.y);
        __nv_bfloat16 h2 = __float2bfloat16(v.z);
        __nv_bfloat16 h3 = __float2bfloat16(v.w);
        __nv_bfloat162 hp0 = {h0, h1}, hp1 = {h2, h3};
        __nv_bfloat162 lp0 = {__float2bfloat16(v.x - __bfloat162float(h0)),
                              __float2bfloat16(v.y - __bfloat162float(h1))};
        __nv_bfloat162 lp1 = {__float2bfloat16(v.z - __bfloat162float(h2)),
                              __float2bfloat16(v.w - __bfloat162float(h3))};
        *reinterpret_cast<__nv_bfloat162*>(hi + off) = hp0;
        *reinterpret_cast<__nv_bfloat162*>(hi + off + 2) = hp1;
        *reinterpret_cast<__nv_bfloat162*>(lo + off) = lp0;
        *reinterpret_cast<__nv_bfloat162*>(lo + off + 2) = lp1;
    };
    auto stsAB = [&](int s) {
        __nv_bfloat16* sAh = smh + s * SC_STAGE;
        __nv_bfloat16* sAl = sAh + SC_REG;
        __nv_bfloat16* sBh = sAl + SC_REG;
        __nv_bfloat16* sBl = sBh + SC_REG;
        #pragma unroll
        for (int j = 0; j < 4; j++) {
            const int off = (prow + 32 * j) * SC_PAD + pkq;
            cvt_store(sAh, sAl, off, na[j]);
            cvt_store(sBh, sBl, off, nb[j]);
        }
    };

    float acc[4][4][4];
    #pragma unroll
    for (int i = 0; i < 4; i++)
        #pragma unroll
        for (int j = 0; j < 4; j++)
            #pragma unroll
            for (int q = 0; q < 4; q++) acc[i][j][q] = 0.f;

    loadAB(0);
    stsAB(0);
    __syncthreads();

    for (int c = 0; c < NC; c++) {
        const int s = c & 1;
        if (c + 1 < NC) loadAB(c + 1);

        const __nv_bfloat16* sAh = smh + s * SC_STAGE;
        const __nv_bfloat16* sAl = sAh + SC_REG;
        const __nv_bfloat16* sBh = sAl + SC_REG;
        const __nv_bfloat16* sBl = sBh + SC_REG;

        #pragma unroll
        for (int ks = 0; ks < 2; ks++) {
            uint32_t ah[4][4], al[4][4], bh[4][2], bl[4][2];
            #pragma unroll
            for (int mf = 0; mf < 4; mf++) {
                const int base = (m_w + mf * 16 + gr) * SC_PAD + ks * 16 + 2 * gc;
                ah[mf][0] = *reinterpret_cast<const uint32_t*>(sAh + base);
                ah[mf][1] = *reinterpret_cast<const uint32_t*>(sAh + base + 8 * SC_PAD);
                ah[mf][2] = *reinterpret_cast<const uint32_t*>(sAh + base + 8);
                ah[mf][3] = *reinterpret_cast<const uint32_t*>(sAh + base + 8 * SC_PAD + 8);
                al[mf][0] = *reinterpret_cast<const uint32_t*>(sAl + base);
                al[mf][1] = *reinterpret_cast<const uint32_t*>(sAl + base + 8 * SC_PAD);
                al[mf][2] = *reinterpret_cast<const uint32_t*>(sAl + base + 8);
                al[mf][3] = *reinterpret_cast<const uint32_t*>(sAl + base + 8 * SC_PAD + 8);
            }
            #pragma unroll
            for (int nf = 0; nf < 4; nf++) {
                const int base = (n_w + nf * 8 + gr) * SC_PAD + ks * 16 + 2 * gc;
                bh[nf][0] = *reinterpret_cast<const uint32_t*>(sBh + base);
                bh[nf][1] = *reinterpret_cast<const uint32_t*>(sBh + base + 8);
                bl[nf][0] = *reinterpret_cast<const uint32_t*>(sBl + base);
                bl[nf][1] = *reinterpret_cast<const uint32_t*>(sBl + base + 8);
            }
            #pragma unroll
            for (int mf = 0; mf < 4; mf++)
                #pragma unroll
                for (int nf = 0; nf < 4; nf++)
                    mma16(acc[mf][nf], ah[mf], bh[nf]);
            #pragma unroll
            for (int mf = 0; mf < 4; mf++)
                #pragma unroll
                for (int nf = 0; nf < 4; nf++)
                    mma16(acc[mf][nf], al[mf], bh[nf]);
            #pragma unroll
            for (int mf = 0; mf < 4; mf++)
                #pragma unroll
                for (int nf = 0; nf < 4; nf++)
                    mma16(acc[mf][nf], ah[mf], bl[nf]);
        }
        if (c + 1 < NC) stsAB(s ^ 1);
        __syncthreads();
    }

    #pragma unroll
    for (int mf = 0; mf < 4; mf++)
        #pragma unroll
        for (int nf = 0; nf < 4; nf++) {
            const int mrow = m_w + mf * 16 + gr;
            const int ncol = n_w + nf * 8 + 2 * gc;
            float2 v0 = make_float2(acc[mf][nf][0], acc[mf][nf][1]);
            float2 v1 = make_float2(acc[mf][nf][2], acc[mf][nf][3]);
            *reinterpret_cast<float2*>(Cbase + (size_t)mrow * c_rs + ncol) = v0;
            *reinterpret_cast<float2*>(Cbase + (size_t)(mrow + 8) * c_rs + ncol) = v1;
        }
}

// ---------------------------------------------------------------------------
// AV GEMM split-BF16: out[t][b][d] = sum_s attn[b][t][s]*values[b][s][d]
// B staged as uint32 k-pair words: word[kp][n] = bf16x2(v[2kp][n], v[2kp+1][n]),
// row pad 136 words -> conflict-free consumer loads, vectorized producer STS.
// ---------------------------------------------------------------------------
static constexpr int AV_A_WPAD = 20;                       // words per A row (40 halves)
static constexpr int AV_A_WORDS = 128 * AV_A_WPAD;         // 2560 words / region
static constexpr int AV_B_WPAD = 136;                      // words per kp row
static constexpr int AV_B_WORDS = 16 * AV_B_WPAD;          // 2176 words / region
static constexpr int AV_STAGE_WORDS = 2 * AV_A_WORDS + 2 * AV_B_WORDS;  // 9472
static constexpr int AV_SMEM = 2 * AV_STAGE_WORDS * 4;     // 75776 bytes

__global__ __launch_bounds__(256) void k_gemm_av(const float* __restrict__ attn,
                                                 const float* __restrict__ values,
                                                 float* __restrict__ out) {
    extern __shared__ uint32_t smw[];
    constexpr int NC = S / KC;   // 64

    const int tid = threadIdx.x;
    const int n0 = blockIdx.x * 128;
    const int m0 = blockIdx.y * 128;
    const int bz = blockIdx.z;

    const float* Abase = attn + ((size_t)bz * T + m0) * S;
    const float* Bbase = values + (size_t)bz * S * D + n0;
    float* Cbase = out + (size_t)m0 * B * D + (size_t)bz * D + n0;
    const size_t c_rs = (size_t)B * D;

    const int lane = tid & 31, wid = tid >> 5;
    const int gr = lane >> 2, gc = lane & 3;
    const int m_w = (wid >> 2) * 64;
    const int n_w = (wid & 3) * 32;

    // A producer: row = tid>>3 (+32/pass), k-quad = (tid&7)*4
    const int prow = tid >> 3;
    const int pkq = (tid & 7) * 4;
    // B producer: kp = tid>>5 (+8 on pass 2), n-quad = (tid&31)*4
    const int bkp = tid >> 5;
    const int bnq = (tid & 31) * 4;

    float4 na[4];
    float4 vb0[2], vb1[2];   // two k-row pairs (passes), each two rows

    auto loadAB = [&](int c) {
        const int k0 = c * KC;
        #pragma unroll
        for (int j = 0; j < 4; j++)
            na[j] = *reinterpret_cast<const float4*>(Abase + (size_t)(prow + 32 * j) * S + k0 + pkq);
        #pragma unroll
        for (int j = 0; j < 2; j++) {
            const int kk = k0 + 2 * (bkp + 8 * j);
            vb0[j] = *reinterpret_cast<const float4*>(Bbase + (size_t)kk * D + bnq);
            vb1[j] = *reinterpret_cast<const float4*>(Bbase + (size_t)(kk + 1) * D + bnq);
        }
    };
    auto stsAB = [&](int s) {
        uint32_t* sAh = smw + s * AV_STAGE_WORDS;
        uint32_t* sAl = sAh + AV_A_WORDS;
        uint32_t* sBh = sAl + AV_A_WORDS;
        uint32_t* sBl = sBh + AV_B_WORDS;
        #pragma unroll
        for (int j = 0; j < 4; j++) {
            const int w = (prow + 32 * j) * AV_A_WPAD + (pkq >> 1);
            const float4 v = na[j];
            __nv_bfloat16 h0 = __float2bfloat16(v.x);
            __nv_bfloat16 h1 = __float2bfloat16(v.y);
            __nv_bfloat16 h2 = __float2bfloat16(v.z);
            __nv_bfloat16 h3 = __float2bfloat16(v.w);
            uint2 hp, lp;
            hp.x = packbf(__bfloat162float(h0), __bfloat162float(h1));
            hp.y = packbf(__bfloat162float(h2), __bfloat162float(h3));
            // direct pack of the already-rounded values (identical bits):
            {
                __nv_bfloat162 t0 = {h0, h1}; hp.x = *reinterpret_cast<uint32_t*>(&t0);
                __nv_bfloat162 t1 = {h2, h3}; hp.y = *reinterpret_cast<uint32_t*>(&t1);
            }
            lp.x = packbf(v.x - __bfloat162float(h0), v.y - __bfloat162float(h1));
            lp.y = packbf(v.z - __bfloat162float(h2), v.w - __bfloat162float(h3));
            *reinterpret_cast<uint2*>(sAh + w) = hp;
            *reinterpret_cast<uint2*>(sAl + w) = lp;
        }
        #pragma unroll
        for (int j = 0; j < 2; j++) {
            const int kp = bkp + 8 * j;
            const int w = kp * AV_B_WPAD + bnq;
            const float4 r0 = vb0[j], r1 = vb1[j];
            const float e0[4] = {r0.x, r0.y, r0.z, r0.w};
            const float e1[4] = {r1.x, r1.y, r1.z, r1.w};
            uint4 hw, lw;
            uint32_t* hwp = reinterpret_cast<uint32_t*>(&hw);
            uint32_t* lwp = reinterpret_cast<uint32_t*>(&lw);
            #pragma unroll
            for (int q = 0; q < 4; q++) {
                __nv_bfloat16 h0 = __float2bfloat16(e0[q]);
                __nv_bfloat16 h1 = __float2bfloat16(e1[q]);
                __nv_bfloat162 th = {h0, h1};
                hwp[q] = *reinterpret_cast<uint32_t*>(&th);
                lwp[q] = packbf(e0[q] - __bfloat162float(h0), e1[q] - __bfloat162float(h1));
            }
            *reinterpret_cast<uint4*>(sBh + w) = hw;
            *reinterpret_cast<uint4*>(sBl + w) = lw;
        }
    };

    float acc[4][4][4];
    #pragma unroll
    for (int i = 0; i < 4; i++)
        #pragma unroll
        for (int j = 0; j < 4; j++)
            #pragma unroll
            for (int q = 0; q < 4; q++) acc[i][j][q] = 0.f;

    loadAB(0);
    stsAB(0);
    __syncthreads();

    for (int c = 0; c < NC; c++) {
        const int s = c & 1;
        if (c + 1 < NC) loadAB(c + 1);

        const uint32_t* sAh = smw + s * AV_STAGE_WORDS;
        const uint32_t* sAl = sAh + AV_A_WORDS;
        const uint32_t* sBh = sAl + AV_A_WORDS;
        const uint32_t* sBl = sBh + AV_B_WORDS;

        #pragma unroll
        for (int ks = 0; ks < 2; ks++) {
            uint32_t ah[4][4], al[4][4], bh[4][2], bl[4][2];
            #pragma unroll
            for (int mf = 0; mf < 4; mf++) {
                const int m = m_w + mf * 16 + gr;
                const int base = m * AV_A_WPAD + ks * 8 + gc;
                ah[mf][0] = sAh[base];
                ah[mf][1] = sAh[base + 8 * AV_A_WPAD];
                ah[mf][2] = sAh[base + 4];
                ah[mf][3] = sAh[base + 8 * AV_A_WPAD + 4];
                al[mf][0] = sAl[base];
                al[mf][1] = sAl[base + 8 * AV_A_WPAD];
                al[mf][2] = sAl[base + 4];
                al[mf][3] = sAl[base + 8 * AV_A_WPAD + 4];
            }
            #pragma unroll
            for (int nf = 0; nf < 4; nf++) {
                const int n = n_w + nf * 8 + gr;
                const int b0 = (ks * 8 + gc) * AV_B_WPAD + n;
                const int b1 = (ks * 8 + gc + 4) * AV_B_WPAD + n;
                bh[nf][0] = sBh[b0];
                bh[nf][1] = sBh[b1];
                bl[nf][0] = sBl[b0];
                bl[nf][1] = sBl[b1];
            }
            #pragma unroll
            for (int mf = 0; mf < 4; mf++)
                #pragma unroll
                for (int nf = 0; nf < 4; nf++)
                    mma16(acc[mf][nf], ah[mf], bh[nf]);
            #pragma unroll
            for (int mf = 0; mf < 4; mf++)
                #pragma unroll
                for (int nf = 0; nf < 4; nf++)
                    mma16(acc[mf][nf], al[mf], bh[nf]);
            #pragma unroll
            for (int mf = 0; mf < 4; mf++)
                #pragma unroll
                for (int nf = 0; nf < 4; nf++)
                    mma16(acc[mf][nf], ah[mf], bl[nf]);
        }
        if (c + 1 < NC) stsAB(s ^ 1);
        __syncthreads();
    }

    #pragma unroll
    for (int mf = 0; mf < 4; mf++)
        #pragma unroll
        for (int nf = 0; nf < 4; nf++) {
            const int mrow = m_w + mf * 16 + gr;
            const int ncol = n_w + nf * 8 + 2 * gc;
            float2 v0 = make_float2(acc[mf][nf][0], acc[mf][nf][1]);
            float2 v1 = make_float2(acc[mf][nf][2], acc[mf][nf][3]);
            *reinterpret_cast<float2*>(Cbase + (size_t)mrow * c_rs + ncol) = v0;
            *reinterpret_cast<float2*>(Cbase + (size_t)(mrow + 8) * c_rs + ncol) = v1;
        }
}

// ---------------------------------------------------------------------------
// LayerNorm in place on g_X rows (B*T rows of D)
// ---------------------------------------------------------------------------
__global__ __launch_bounds__(256) void k_ln(const float* __restrict__ gamma,
                                            const float* __restrict__ beta) {
    const int row = blockIdx.x;
    float* x = &g_X[(size_t)row * D];
    const int tid = threadIdx.x;

    float2 v = *reinterpret_cast<const float2*>(&x[tid * 2]);
    float s = v.x + v.y;
    float q = v.x * v.x + v.y * v.y;

    __shared__ float sh_s[8], sh_q[8];
    #pragma unroll
    for (int o = 16; o > 0; o >>= 1) {
        s += __shfl_xor_sync(0xffffffffu, s, o);
        q += __shfl_xor_sync(0xffffffffu, q, o);
    }
    if ((tid & 31) == 0) { sh_s[tid >> 5] = s; sh_q[tid >> 5] = q; }
    __syncthreads();
    float ts = 0.f, tq = 0.f;
    #pragma unroll
    for (int i = 0; i < 8; i++) { ts += sh_s[i]; tq += sh_q[i]; }

    const float mean = ts * (1.0f / D);
    const float var = tq * (1.0f / D) - mean * mean;
    const float rstd = rsqrtf(var + LN_EPS);

    float2 g = *reinterpret_cast<const float2*>(&gamma[tid * 2]);
    float2 bb = *reinterpret_cast<const float2*>(&beta[tid * 2]);
    float2 o;
    o.x = g.x * (v.x - mean) * rstd + bb.x;
    o.y = g.y * (v.y - mean) * rstd + bb.y;
    *reinterpret_cast<float2*>(&x[tid * 2]) = o;
}

// ---------------------------------------------------------------------------
// Softmax over S for each of B*T rows, in place
// ---------------------------------------------------------------------------
__global__ __launch_bounds__(256) void k_softmax(float* __restrict__ attn) {
    const size_t row = blockIdx.x;
    float* p = attn + row * (size_t)S;
    const int tid = threadIdx.x;

    float4 v0 = reinterpret_cast<const float4*>(p)[tid * 2 + 0];
    float4 v1 = reinterpret_cast<const float4*>(p)[tid * 2 + 1];

    float m = fmaxf(fmaxf(fmaxf(v0.x, v0.y), fmaxf(v0.z, v0.w)),
                    fmaxf(fmaxf(v1.x, v1.y), fmaxf(v1.z, v1.w)));
    __shared__ float sh[8];
    #pragma unroll
    for (int o = 16; o > 0; o >>= 1) m = fmaxf(m, __shfl_xor_sync(0xffffffffu, m, o));
    if ((tid & 31) == 0) sh[tid >> 5] = m;
    __syncthreads();
    float gm = sh[0];
    #pragma unroll
    for (int i = 1; i < 8; i++) gm = fmaxf(gm, sh[i]);
    __syncthreads();

    v0.x = __expf(v0.x - gm); v0.y = __expf(v0.y - gm);
    v0.z = __expf(v0.z - gm); v0.w = __expf(v0.w - gm);
    v1.x = __expf(v1.x - gm); v1.y = __expf(v1.y - gm);
    v1.z = __expf(v1.z - gm); v1.w = __expf(v1.w - gm);

    float s = v0.x + v0.y + v0.z + v0.w + v1.x + v1.y + v1.z + v1.w;
    #pragma unroll
    for (int o = 16; o > 0; o >>= 1) s += __shfl_xor_sync(0xffffffffu, s, o);
    if ((tid & 31) == 0) sh[tid >> 5] = s;
    __syncthreads();
    float gs = 0.f;
    #pragma unroll
    for (int i = 0; i < 8; i++) gs += sh[i];
    const float inv = 1.0f / gs;

    v0.x *= inv; v0.y *= inv; v0.z *= inv; v0.w *= inv;
    v1.x *= inv; v1.y *= inv; v1.z *= inv; v1.w *= inv;
    reinterpret_cast<float4*>(p)[tid * 2 + 0] = v0;
    reinterpret_cast<float4*>(p)[tid * 2 + 1] = v1;
}

// ---------------------------------------------------------------------------
extern "C" void kernel_launch(void* const* d_in, const int* in_sizes, int n_in,
                              void* d_out, int out_size) {
    const float* inp    = (const float*)d_in[0];  // [T,B,D]
    const float* ctx    = (const float*)d_in[1];  // [B,S,D]
    const float* values = (const float*)d_in[2];  // [B,S,D]
    const float* W      = (const float*)d_in[3];  // [D,D]
    const float* gamma  = (const float*)d_in[4];  // [D]
    const float* beta   = (const float*)d_in[5];  // [D]

    float* out_wc   = (float*)d_out;                       // [T,B,D]
    float* out_attn = (float*)d_out + (size_t)T * B * D;   // [B*T,S]

    cudaFuncSetAttribute(k_gemm_nt<0>, cudaFuncAttributeMaxDynamicSharedMemorySize, SC_SMEM);
    cudaFuncSetAttribute(k_gemm_nt<1>, cudaFuncAttributeMaxDynamicSharedMemorySize, SC_SMEM);
    cudaFuncSetAttribute(k_gemm_av, cudaFuncAttributeMaxDynamicSharedMemorySize, AV_SMEM);

    // 1) linear: g_X = inp @ W^T (rows b*T+t)  [bf16x3]
    {
        dim3 grid(D / 128, (B * T) / 128, 1);
        k_gemm_nt<0><<<grid, 256, SC_SMEM>>>(inp, W, nullptr);
    }
    // 2) LayerNorm in place
    k_ln<<<B * T, 256>>>(gamma, beta);
    // 3) scores -> attn region  [bf16x3]
    {
        dim3 grid(S / 128, T / 128, B);
        k_gemm_nt<1><<<grid, 256, SC_SMEM>>>(nullptr, ctx, out_attn);
    }
    // 4) softmax in place
    k_softmax<<<B * T, 256>>>(out_attn);
    // 5) weightedContext  [bf16x3, vectorized B staging]
    {
        dim3 grid(D / 128, T / 128, B);
        k_gemm_av<<<grid, 256, AV_SMEM>>>(out_attn, values, out_wc);
    }
}